// round 2
// baseline (speedup 1.0000x reference)
#include <cuda_runtime.h>
#include <cuda_bf16.h>
#include <math.h>

#define BB 2
#define NP 150000
#define HW 262144
#define NSEG (HW + 1)

struct Scratch {
    double bn1[BB * 64];          // [b][ sum(32) | sumsq(32) ]
    double bn2[BB * 128];         // [b][ sum(64) | sumsq(64) ]
    unsigned int nvalid[BB];
    unsigned int pad_;
    float cnt[BB * NSEG];
    float sumxyz[BB * NSEG * 3];
    float p1sum[BB * NSEG * 32];
    float p1max[BB * NSEG * 32];
    float p2sum[(size_t)BB * NSEG * 64];
    float p2max[(size_t)BB * NSEG * 64];
};

__device__ Scratch g_s;
__device__ int   g_vid[BB * NP];
__device__ float g_x1[BB * NP * 32];
__device__ float g_x2[(size_t)BB * NP * 64];
__device__ float g_bn1ss[BB * 64];    // [b][ scale(32) | shift(32) ]
__device__ float g_bn2ss[BB * 128];   // [b][ scale(64) | shift(64) ]

// ---------------- kernel A: voxelize + counts + sum_xyz ----------------
__global__ void kA(const float* __restrict__ pts) {
    int b = blockIdx.y;
    int i = blockIdx.x * blockDim.x + threadIdx.x;
    bool act = (i < NP);
    bool valid = false;
    if (act) {
        const float* p = pts + ((long)b * NP + i) * 3;
        float p0 = p[0], p1 = p[1], p2 = p[2];
        float fx = floorf((p0 - (-51.2f)) / 0.2f);
        float fy = floorf((p1 - (-51.2f)) / 0.2f);
        float fz = floorf((p2 - (-3.0f)) / 6.0f);
        valid = (fx >= 0.f) && (fx < 512.f) && (fy >= 0.f) && (fy < 512.f) &&
                (fz >= 0.f) && (fz < 1.f);
        int vid = HW;
        if (valid) {
            int cx = (int)fx, cy = (int)fy;
            vid = cy * 512 + cx;
            atomicAdd(&g_s.cnt[b * NSEG + vid], 1.0f);
            float* sx = &g_s.sumxyz[((long)b * NSEG + vid) * 3];
            atomicAdd(sx + 0, p0);
            atomicAdd(sx + 1, p1);
            atomicAdd(sx + 2, p2);
        }
        g_vid[b * NP + i] = vid;
    }
    unsigned bal = __ballot_sync(0xffffffffu, act && valid);
    if ((threadIdx.x & 31) == 0 && bal)
        atomicAdd(&g_s.nvalid[b], (unsigned)__popc(bal));
}

// ---------------- kernel B: feats @ W1, BN1 stats ----------------
__global__ void kB(const float* __restrict__ pts, const float* __restrict__ W1) {
    __shared__ float w[9 * 32];
    __shared__ float ssum[32], ssq[32];
    int t = threadIdx.x;
    for (int k = t; k < 9 * 32; k += blockDim.x) w[k] = W1[k];   // FIX: 288 > 256
    if (t < 32) { ssum[t] = 0.f; ssq[t] = 0.f; }
    __syncthreads();
    int b = blockIdx.y;
    int g = blockIdx.x * blockDim.x + t;
    int i = g >> 5;
    int c = t & 31;
    float x = 0.f;
    if (i < NP) {
        int vid = g_vid[b * NP + i];
        if (vid < HW) {
            const float* p = pts + ((long)b * NP + i) * 3;
            float p0 = p[0], p1 = p[1], p2 = p[2];
            float cntv = g_s.cnt[b * NSEG + vid];
            float inv = 1.0f / fmaxf(cntv, 1.0f);
            const float* sx = &g_s.sumxyz[((long)b * NSEG + vid) * 3];
            float m0 = sx[0] * inv, m1 = sx[1] * inv, m2 = sx[2] * inv;
            int cx = vid & 511, cy = vid >> 9;
            float cpx = -51.2f + ((float)cx + 0.5f) * 0.2f;
            float cpy = -51.2f + ((float)cy + 0.5f) * 0.2f;
            float f[9] = { p0, p1, p2, p0 - m0, p1 - m1, p2 - m2,
                           p0 - cpx, p1 - cpy, p2 };
#pragma unroll
            for (int k = 0; k < 9; k++) x += f[k] * w[k * 32 + c];
        }
        g_x1[((long)b * NP + i) * 32 + c] = x;
        atomicAdd(&ssum[c], x);
        atomicAdd(&ssq[c], x * x);
    }
    __syncthreads();
    if (t < 32) {
        atomicAdd(&g_s.bn1[b * 64 + t], (double)ssum[t]);
        atomicAdd(&g_s.bn1[b * 64 + 32 + t], (double)ssq[t]);
    }
}

// ---------------- BN finalize: scale/shift ----------------
__global__ void kBN(int which, const float* __restrict__ gam,
                    const float* __restrict__ bet) {
    int t = threadIdx.x;
    int C = which ? 64 : 32;
    int b = t / C, c = t % C;
    if (b >= BB) return;
    float nv = fmaxf((float)g_s.nvalid[b], 1.0f);
    double s, sq;
    if (which) { s = g_s.bn2[b * 128 + c]; sq = g_s.bn2[b * 128 + 64 + c]; }
    else       { s = g_s.bn1[b * 64 + c];  sq = g_s.bn1[b * 64 + 32 + c]; }
    float mean = (float)(s / (double)nv);
    float var = (float)(sq / (double)nv) - mean * mean;
    var = fmaxf(var, 0.f);
    float sc = gam[c] * rsqrtf(var + 0.001f);
    float sh = bet[c] - mean * sc;
    if (which) { g_bn2ss[b * 128 + c] = sc; g_bn2ss[b * 128 + 64 + c] = sh; }
    else       { g_bn1ss[b * 64 + c] = sc;  g_bn1ss[b * 64 + 32 + c] = sh; }
}

// ---------------- kernel D: BN1+ReLU+mask, scatter pool1 ----------------
__global__ void kD() {
    int b = blockIdx.y;
    int t = threadIdx.x;
    int g = blockIdx.x * blockDim.x + t;
    int i = g >> 5;
    int c = t & 31;
    if (i >= NP) return;
    int vid = g_vid[b * NP + i];
    float y = 0.f;
    long xo = ((long)b * NP + i) * 32 + c;
    if (vid < HW) {
        float x = g_x1[xo];
        y = fmaxf(x * g_bn1ss[b * 64 + c] + g_bn1ss[b * 64 + 32 + c], 0.f);
        long o = ((long)b * NSEG + vid) * 32 + c;
        atomicAdd(&g_s.p1sum[o], y);
        atomicMax((int*)&g_s.p1max[o], __float_as_int(y));
    }
    g_x1[xo] = y;
}

// ---------------- kernel E: x1c @ W2, BN2 stats ----------------
__global__ void kE(const float* __restrict__ W2) {
    __shared__ float w[64 * 64];
    __shared__ float ss[64], sq[64];
    int t = threadIdx.x, b = blockIdx.y;
    for (int k = t; k < 4096; k += 256) w[k] = W2[k];
    if (t < 64) { ss[t] = 0.f; sq[t] = 0.f; }
    __syncthreads();
    int warp = t >> 5, lane = t & 31;
    int i = blockIdx.x * 8 + warp;
    if (i < NP) {
        int vid = g_vid[b * NP + i];
        float a0 = 0.f, a1 = 0.f;
        if (vid < HW) {
            a0 = g_x1[((long)b * NP + i) * 32 + lane];
            long o = ((long)b * NSEG + vid) * 32 + lane;
            float inv = 1.0f / fmaxf(g_s.cnt[b * NSEG + vid], 1.0f);
            a1 = 0.5f * (g_s.p1max[o] + g_s.p1sum[o] * inv);
        }
        float olo = 0.f, ohi = 0.f;
#pragma unroll
        for (int k = 0; k < 32; k++) {
            float bk = __shfl_sync(0xffffffffu, a0, k);
            olo += bk * w[k * 64 + lane];
            ohi += bk * w[k * 64 + 32 + lane];
        }
#pragma unroll
        for (int k = 0; k < 32; k++) {
            float bk = __shfl_sync(0xffffffffu, a1, k);
            olo += bk * w[(32 + k) * 64 + lane];
            ohi += bk * w[(32 + k) * 64 + 32 + lane];
        }
        size_t o2 = ((size_t)b * NP + i) * 64;
        g_x2[o2 + lane] = olo;
        g_x2[o2 + 32 + lane] = ohi;
        atomicAdd(&ss[lane], olo);
        atomicAdd(&ss[lane + 32], ohi);
        atomicAdd(&sq[lane], olo * olo);
        atomicAdd(&sq[lane + 32], ohi * ohi);
    }
    __syncthreads();
    if (t < 64) {
        atomicAdd(&g_s.bn2[b * 128 + t], (double)ss[t]);
        atomicAdd(&g_s.bn2[b * 128 + 64 + t], (double)sq[t]);
    }
}

// ---------------- kernel G: BN2+ReLU+mask, scatter pool2 ----------------
__global__ void kG() {
    int b = blockIdx.y;
    long g = (long)blockIdx.x * blockDim.x + threadIdx.x;
    int i = (int)(g >> 6);
    int c = (int)(g & 63);
    if (i >= NP) return;
    int vid = g_vid[b * NP + i];
    if (vid >= HW) return;
    float x = g_x2[((size_t)b * NP + i) * 64 + c];
    float y = fmaxf(x * g_bn2ss[b * 128 + c] + g_bn2ss[b * 128 + 64 + c], 0.f);
    size_t o = ((size_t)b * NSEG + vid) * 64 + c;
    atomicAdd(&g_s.p2sum[o], y);
    atomicMax((int*)&g_s.p2max[o], __float_as_int(y));
}

// ---------------- kernel H: mix-pool2 + transpose to [B,64,H,W] ----------------
__global__ void kH(float* __restrict__ out) {
    __shared__ float sT[64][33];
    __shared__ float scnt[32];
    int t = threadIdx.x;
    int b = blockIdx.y;
    int vb = blockIdx.x * 32;
    if (t < 32) scnt[t] = fmaxf(g_s.cnt[b * NSEG + vb + t], 1.0f);
    __syncthreads();
#pragma unroll
    for (int r = 0; r < 8; r++) {
        int j = t + 256 * r;
        int v = j >> 6, c = j & 63;
        size_t o = ((size_t)b * NSEG + vb + v) * 64 + c;
        float val = 0.5f * (g_s.p2max[o] + g_s.p2sum[o] / scnt[v]);
        sT[c][v] = val;
    }
    __syncthreads();
#pragma unroll
    for (int r = 0; r < 8; r++) {
        int j = t + 256 * r;
        int c = j >> 5, v = j & 31;
        out[((size_t)b * 64 + c) * HW + vb + v] = sT[c][v];
    }
}

extern "C" void kernel_launch(void* const* d_in, const int* in_sizes, int n_in,
                              void* d_out, int out_size) {
    const float* pts = (const float*)d_in[0];
    const float* W1 = (const float*)d_in[1];
    const float* g1 = (const float*)d_in[2];
    const float* b1 = (const float*)d_in[3];
    const float* W2 = (const float*)d_in[4];
    const float* g2 = (const float*)d_in[5];
    const float* b2 = (const float*)d_in[6];
    float* out = (float*)d_out;

    void* sp = nullptr;
    cudaGetSymbolAddress(&sp, g_s);
    cudaMemsetAsync(sp, 0, sizeof(Scratch));

    dim3 gA((NP + 255) / 256, BB);
    kA<<<gA, 256>>>(pts);

    dim3 gB((NP * 32 + 255) / 256, BB);
    kB<<<gB, 256>>>(pts, W1);

    kBN<<<1, BB * 32>>>(0, g1, b1);

    kD<<<gB, 256>>>();

    dim3 gE((NP + 7) / 8, BB);
    kE<<<gE, 256>>>(W2);

    kBN<<<1, BB * 64>>>(1, g2, b2);

    dim3 gG((int)(((long)NP * 64 + 255) / 256), BB);
    kG<<<gG, 256>>>();

    dim3 gH(HW / 32, BB);
    kH<<<gH, 256>>>(out);
}

// round 4
// speedup vs baseline: 1.0811x; 1.0811x over previous
#include <cuda_runtime.h>
#include <cuda_bf16.h>
#include <math.h>

#define BB 2
#define NP 150000
#define HW 262144
#define NSEG (HW + 1)
#define SCAN_N (BB * NSEG)
#define SCAN_B 1024
#define SCAN_NB ((SCAN_N + SCAN_B - 1) / SCAN_B)

struct Scratch {
    double bn1[BB * 64];           // [b][ sum(32) | sumsq(32) ]
    double bn2[BB * 128];          // [b][ sum(64) | sumsq(64) ]
    int    cnt[BB * NSEG];
    float  sumxyz[BB * NSEG * 3];
};

__device__ Scratch g_s;
__device__ int   g_start[SCAN_N];       // scan: exclusive start; after scatter: end
__device__ int   g_bsum[SCAN_NB];
__device__ int   g_order[BB * NP];      // point idx (local to batch), CSR-sorted
__device__ int   g_vid[BB * NP];
__device__ float g_x1[BB * NP * 32];                 // raw (pre-BN)
__device__ float g_x2[(size_t)BB * NP * 64];         // raw (pre-BN)
__device__ float g_p1mix[(size_t)BB * HW * 32];      // only occupied voxels written
__device__ float g_bn1ss[BB * 64];     // [b][ scale(32) | shift(32) ]
__device__ float g_bn2ss[BB * 128];    // [b][ scale(64) | shift(64) ]

// ---------------- kA: voxelize + counts + sum_xyz ----------------
__global__ void kA(const float* __restrict__ pts) {
    int b = blockIdx.y;
    int i = blockIdx.x * blockDim.x + threadIdx.x;
    if (i >= NP) return;
    const float* p = pts + ((long)b * NP + i) * 3;
    float p0 = p[0], p1 = p[1], p2 = p[2];
    float fx = floorf((p0 + 51.2f) / 0.2f);
    float fy = floorf((p1 + 51.2f) / 0.2f);
    float fz = floorf((p2 + 3.0f) / 6.0f);
    bool valid = (fx >= 0.f) && (fx < 512.f) && (fy >= 0.f) && (fy < 512.f) &&
                 (fz >= 0.f) && (fz < 1.f);
    int vid = HW;
    if (valid) {
        vid = (int)fy * 512 + (int)fx;
        float* sx = &g_s.sumxyz[((long)b * NSEG + vid) * 3];
        atomicAdd(sx + 0, p0);
        atomicAdd(sx + 1, p1);
        atomicAdd(sx + 2, p2);
    }
    atomicAdd(&g_s.cnt[b * NSEG + vid], 1);
    g_vid[b * NP + i] = vid;
}

// ---------------- scan helpers ----------------
__device__ __forceinline__ int blockScanExcl(int v, int t, int* ws) {
    int lane = t & 31, w = t >> 5;
    int inc = v;
#pragma unroll
    for (int o = 1; o < 32; o <<= 1) {
        int n = __shfl_up_sync(0xffffffffu, inc, o);
        if (lane >= o) inc += n;
    }
    if (lane == 31) ws[w] = inc;
    __syncthreads();
    if (w == 0) {
        int s = ws[lane];
#pragma unroll
        for (int o = 1; o < 32; o <<= 1) {
            int n = __shfl_up_sync(0xffffffffu, s, o);
            if (lane >= o) s += n;
        }
        ws[lane] = s;
    }
    __syncthreads();
    return (w ? ws[w - 1] : 0) + inc - v;
}

__global__ void kS1() {
    __shared__ int ws[32];
    int t = threadIdx.x;
    int idx = blockIdx.x * SCAN_B + t;
    int v = (idx < SCAN_N) ? g_s.cnt[idx] : 0;
    int ex = blockScanExcl(v, t, ws);
    if (idx < SCAN_N) g_start[idx] = ex;
    if (t == 0) g_bsum[blockIdx.x] = ws[31];
}

__global__ void kS2() {
    __shared__ int ws[32];
    int t = threadIdx.x;
    int v = (t < SCAN_NB) ? g_bsum[t] : 0;
    int ex = blockScanExcl(v, t, ws);
    if (t < SCAN_NB) g_bsum[t] = ex;
}

__global__ void kS3() {
    int idx = blockIdx.x * SCAN_B + threadIdx.x;
    if (idx < SCAN_N) g_start[idx] += g_bsum[blockIdx.x];
}

// ---------------- scatter: build CSR order ----------------
__global__ void kSc() {
    int b = blockIdx.y;
    int i = blockIdx.x * blockDim.x + threadIdx.x;
    if (i >= NP) return;
    int vid = g_vid[b * NP + i];
    int slot = atomicAdd(&g_start[b * NSEG + vid], 1);
    g_order[slot] = i;       // g_start becomes END after this kernel
}

// ---------------- kB: feats @ W1 (raw), BN1 stats ----------------
__global__ void kB(const float* __restrict__ pts, const float* __restrict__ W1) {
    __shared__ float w[9 * 32];
    __shared__ float ssum[32], ssq[32];
    int t = threadIdx.x;
    for (int k = t; k < 9 * 32; k += blockDim.x) w[k] = W1[k];
    if (t < 32) { ssum[t] = 0.f; ssq[t] = 0.f; }
    __syncthreads();
    int b = blockIdx.y;
    int g = blockIdx.x * blockDim.x + t;
    int i = g >> 5;
    int c = t & 31;
    float x = 0.f;
    if (i < NP) {
        int vid = g_vid[b * NP + i];
        if (vid < HW) {
            const float* p = pts + ((long)b * NP + i) * 3;
            float p0 = p[0], p1 = p[1], p2 = p[2];
            float inv = 1.0f / fmaxf((float)g_s.cnt[b * NSEG + vid], 1.0f);
            const float* sx = &g_s.sumxyz[((long)b * NSEG + vid) * 3];
            float m0 = sx[0] * inv, m1 = sx[1] * inv, m2 = sx[2] * inv;
            int cx = vid & 511, cy = vid >> 9;
            float cpx = -51.2f + ((float)cx + 0.5f) * 0.2f;
            float cpy = -51.2f + ((float)cy + 0.5f) * 0.2f;
            float f[9] = { p0, p1, p2, p0 - m0, p1 - m1, p2 - m2,
                           p0 - cpx, p1 - cpy, p2 };
#pragma unroll
            for (int k = 0; k < 9; k++) x += f[k] * w[k * 32 + c];
        }
        g_x1[((long)b * NP + i) * 32 + c] = x;
        atomicAdd(&ssum[c], x);
        atomicAdd(&ssq[c], x * x);
    }
    __syncthreads();
    if (t < 32) {
        atomicAdd(&g_s.bn1[b * 64 + t], (double)ssum[t]);
        atomicAdd(&g_s.bn1[b * 64 + 32 + t], (double)ssq[t]);
    }
}

// ---------------- BN finalize ----------------
__global__ void kBN(int which, const float* __restrict__ gam,
                    const float* __restrict__ bet) {
    int t = threadIdx.x;
    int C = which ? 64 : 32;
    int b = t / C, c = t % C;
    if (b >= BB) return;
    float nv = fmaxf((float)(NP - g_s.cnt[b * NSEG + HW]), 1.0f);
    double s, sq;
    if (which) { s = g_s.bn2[b * 128 + c]; sq = g_s.bn2[b * 128 + 64 + c]; }
    else       { s = g_s.bn1[b * 64 + c];  sq = g_s.bn1[b * 64 + 32 + c]; }
    float mean = (float)(s / (double)nv);
    float var = (float)(sq / (double)nv) - mean * mean;
    var = fmaxf(var, 0.f);
    float sc = gam[c] * rsqrtf(var + 0.001f);
    float sh = bet[c] - mean * sc;
    if (which) { g_bn2ss[b * 128 + c] = sc; g_bn2ss[b * 128 + 64 + c] = sh; }
    else       { g_bn1ss[b * 64 + c] = sc;  g_bn1ss[b * 64 + 32 + c] = sh; }
}

// ---------------- kP1: CSR mix-pool1 (warp per voxel) ----------------
__global__ void kP1() {
    int b = blockIdx.y;
    int t = threadIdx.x;
    int w = t >> 5, lane = t & 31;
    int v = blockIdx.x * 8 + w;
    int base = b * NSEG + v;
    int cnt = g_s.cnt[base];
    if (cnt == 0) return;
    int end = g_start[base], beg = end - cnt;
    float sc = g_bn1ss[b * 64 + lane], sh = g_bn1ss[b * 64 + 32 + lane];
    float s = 0.f, m = 0.f;
    for (int j = beg; j < end; j++) {
        int pt = g_order[j];
        float x = g_x1[((long)b * NP + pt) * 32 + lane];
        float y = fmaxf(x * sc + sh, 0.f);
        s += y; m = fmaxf(m, y);
    }
    g_p1mix[((size_t)b * HW + v) * 32 + lane] = 0.5f * (m + s / (float)cnt);
}

// ---------------- kE: x1c @ W2 (raw), BN2 stats ----------------
__global__ void kE(const float* __restrict__ W2) {
    __shared__ float w[64 * 64];
    __shared__ float ss[64], sq[64];
    int t = threadIdx.x, b = blockIdx.y;
    for (int k = t; k < 4096; k += 256) w[k] = W2[k];
    if (t < 64) { ss[t] = 0.f; sq[t] = 0.f; }
    __syncthreads();
    int warp = t >> 5, lane = t & 31;
    int i = blockIdx.x * 8 + warp;
    if (i < NP) {
        int vid = g_vid[b * NP + i];
        float a0 = 0.f, a1 = 0.f;
        if (vid < HW) {
            float x = g_x1[((long)b * NP + i) * 32 + lane];
            float sc = g_bn1ss[b * 64 + lane], sh = g_bn1ss[b * 64 + 32 + lane];
            a0 = fmaxf(x * sc + sh, 0.f);
            a1 = g_p1mix[((size_t)b * HW + vid) * 32 + lane];
        }
        float olo = 0.f, ohi = 0.f;
#pragma unroll
        for (int k = 0; k < 32; k++) {
            float bk = __shfl_sync(0xffffffffu, a0, k);
            olo += bk * w[k * 64 + lane];
            ohi += bk * w[k * 64 + 32 + lane];
        }
#pragma unroll
        for (int k = 0; k < 32; k++) {
            float bk = __shfl_sync(0xffffffffu, a1, k);
            olo += bk * w[(32 + k) * 64 + lane];
            ohi += bk * w[(32 + k) * 64 + 32 + lane];
        }
        size_t o2 = ((size_t)b * NP + i) * 64;
        g_x2[o2 + lane] = olo;
        g_x2[o2 + 32 + lane] = ohi;
        atomicAdd(&ss[lane], olo);
        atomicAdd(&ss[lane + 32], ohi);
        atomicAdd(&sq[lane], olo * olo);
        atomicAdd(&sq[lane + 32], ohi * ohi);
    }
    __syncthreads();
    if (t < 64) {
        atomicAdd(&g_s.bn2[b * 128 + t], (double)ss[t]);
        atomicAdd(&g_s.bn2[b * 128 + 64 + t], (double)sq[t]);
    }
}

// ---------------- kP2T: CSR mix-pool2 + transpose to [B,64,H,W] ----------------
__global__ void kP2T(float* __restrict__ out) {
    __shared__ float sT[64][33];
    int b = blockIdx.y, t = threadIdx.x;
    int vb = blockIdx.x * 32;
    int sub = t >> 6, c = t & 63;
    float sc = g_bn2ss[b * 128 + c], sh = g_bn2ss[b * 128 + 64 + c];
#pragma unroll
    for (int g8 = 0; g8 < 8; g8++) {
        int v = vb + g8 * 4 + sub;
        int base = b * NSEG + v;
        int cnt = g_s.cnt[base];
        float val = 0.f;
        if (cnt > 0) {
            int end = g_start[base], beg = end - cnt;
            float s = 0.f, m = 0.f;
            for (int j = beg; j < end; j++) {
                int pt = g_order[j];
                float x = g_x2[((size_t)b * NP + pt) * 64 + c];
                float y = fmaxf(x * sc + sh, 0.f);
                s += y; m = fmaxf(m, y);
            }
            val = 0.5f * (m + s / (float)cnt);
        }
        sT[c][g8 * 4 + sub] = val;
    }
    __syncthreads();
#pragma unroll
    for (int r = 0; r < 8; r++) {
        int j = t + 256 * r;
        int cc = j >> 5, v = j & 31;
        out[((size_t)b * 64 + cc) * HW + vb + v] = sT[cc][v];
    }
}

extern "C" void kernel_launch(void* const* d_in, const int* in_sizes, int n_in,
                              void* d_out, int out_size) {
    const float* pts = (const float*)d_in[0];
    const float* W1 = (const float*)d_in[1];
    const float* g1 = (const float*)d_in[2];
    const float* b1 = (const float*)d_in[3];
    const float* W2 = (const float*)d_in[4];
    const float* g2 = (const float*)d_in[5];
    const float* b2 = (const float*)d_in[6];
    float* out = (float*)d_out;

    void* sp = nullptr;
    cudaGetSymbolAddress(&sp, g_s);
    cudaMemsetAsync(sp, 0, sizeof(Scratch));

    dim3 gA((NP + 255) / 256, BB);
    kA<<<gA, 256>>>(pts);

    kS1<<<SCAN_NB, SCAN_B>>>();
    kS2<<<1, SCAN_B>>>();
    kS3<<<SCAN_NB, SCAN_B>>>();
    kSc<<<gA, 256>>>();

    dim3 gB((NP * 32 + 255) / 256, BB);
    kB<<<gB, 256>>>(pts, W1);

    kBN<<<1, BB * 32>>>(0, g1, b1);

    dim3 gP1(HW / 8, BB);
    kP1<<<gP1, 256>>>();

    dim3 gE((NP + 7) / 8, BB);
    kE<<<gE, 256>>>(W2);

    kBN<<<1, BB * 64>>>(1, g2, b2);

    dim3 gP2(HW / 32, BB);
    kP2T<<<gP2, 256>>>(out);
}

// round 5
// speedup vs baseline: 2.0227x; 1.8710x over previous
#include <cuda_runtime.h>
#include <cuda_bf16.h>
#include <math.h>

#define BB 2
#define NP 150000
#define HW 262144
#define NSEG (HW + 1)
#define SCAN_N (BB * NSEG)
#define SCAN_B 1024
#define SCAN_NB ((SCAN_N + SCAN_B - 1) / SCAN_B)
#define NBUCK 128

struct Scratch {
    double bnb1[NBUCK][BB * 64];    // buckets: [b][ sum(32) | sumsq(32) ]
    double bnb2[NBUCK][BB * 128];   // buckets: [b][ sum(64) | sumsq(64) ]
    int    cnt[BB * NSEG];
    float  sumxyz[BB * NSEG * 3];
};

__device__ Scratch g_s;
__device__ int   g_start[SCAN_N];       // scan: exclusive start; after scatter: end
__device__ int   g_bsum[SCAN_NB];
__device__ int   g_order[BB * NP];      // point idx (local to batch), CSR-sorted
__device__ int   g_vid[BB * NP];
__device__ float g_x1[BB * NP * 32];                 // raw (pre-BN)
__device__ float g_x2[(size_t)BB * NP * 64];         // raw (pre-BN)
__device__ float g_p1mix[(size_t)BB * HW * 32];      // only occupied voxels written
__device__ float g_bn1ss[BB * 64];     // [b][ scale(32) | shift(32) ]
__device__ float g_bn2ss[BB * 128];    // [b][ scale(64) | shift(64) ]

// ---------------- kA: voxelize + counts + sum_xyz ----------------
__global__ void kA(const float* __restrict__ pts) {
    int b = blockIdx.y;
    int i = blockIdx.x * blockDim.x + threadIdx.x;
    if (i >= NP) return;
    const float* p = pts + ((long)b * NP + i) * 3;
    float p0 = p[0], p1 = p[1], p2 = p[2];
    float fx = floorf((p0 + 51.2f) / 0.2f);
    float fy = floorf((p1 + 51.2f) / 0.2f);
    float fz = floorf((p2 + 3.0f) / 6.0f);
    bool valid = (fx >= 0.f) && (fx < 512.f) && (fy >= 0.f) && (fy < 512.f) &&
                 (fz >= 0.f) && (fz < 1.f);
    int vid = HW;
    if (valid) {
        vid = (int)fy * 512 + (int)fx;
        float* sx = &g_s.sumxyz[((long)b * NSEG + vid) * 3];
        atomicAdd(sx + 0, p0);
        atomicAdd(sx + 1, p1);
        atomicAdd(sx + 2, p2);
    }
    atomicAdd(&g_s.cnt[b * NSEG + vid], 1);
    g_vid[b * NP + i] = vid;
}

// ---------------- scan helpers ----------------
__device__ __forceinline__ int blockScanExcl(int v, int t, int* ws) {
    int lane = t & 31, w = t >> 5;
    int inc = v;
#pragma unroll
    for (int o = 1; o < 32; o <<= 1) {
        int n = __shfl_up_sync(0xffffffffu, inc, o);
        if (lane >= o) inc += n;
    }
    if (lane == 31) ws[w] = inc;
    __syncthreads();
    if (w == 0) {
        int s = ws[lane];
#pragma unroll
        for (int o = 1; o < 32; o <<= 1) {
            int n = __shfl_up_sync(0xffffffffu, s, o);
            if (lane >= o) s += n;
        }
        ws[lane] = s;
    }
    __syncthreads();
    return (w ? ws[w - 1] : 0) + inc - v;
}

__global__ void kS1() {
    __shared__ int ws[32];
    int t = threadIdx.x;
    int idx = blockIdx.x * SCAN_B + t;
    int v = (idx < SCAN_N) ? g_s.cnt[idx] : 0;
    int ex = blockScanExcl(v, t, ws);
    if (idx < SCAN_N) g_start[idx] = ex;
    if (t == 0) g_bsum[blockIdx.x] = ws[31];
}

__global__ void kS2() {
    __shared__ int ws[32];
    int t = threadIdx.x;
    int v = (t < SCAN_NB) ? g_bsum[t] : 0;
    int ex = blockScanExcl(v, t, ws);
    if (t < SCAN_NB) g_bsum[t] = ex;
}

__global__ void kS3() {
    int idx = blockIdx.x * SCAN_B + threadIdx.x;
    if (idx < SCAN_N) g_start[idx] += g_bsum[blockIdx.x];
}

// ---------------- scatter: build CSR order ----------------
__global__ void kSc() {
    int b = blockIdx.y;
    int i = blockIdx.x * blockDim.x + threadIdx.x;
    if (i >= NP) return;
    int vid = g_vid[b * NP + i];
    int slot = atomicAdd(&g_start[b * NSEG + vid], 1);
    g_order[slot] = i;       // g_start becomes END after this kernel
}

// ---------------- kB: feats @ W1 (raw), BN1 stats (bucketed) ----------------
__global__ void kB(const float* __restrict__ pts, const float* __restrict__ W1) {
    __shared__ float w[9 * 32];
    __shared__ float ssum[32], ssq[32];
    int t = threadIdx.x;
    for (int k = t; k < 9 * 32; k += blockDim.x) w[k] = W1[k];
    if (t < 32) { ssum[t] = 0.f; ssq[t] = 0.f; }
    __syncthreads();
    int b = blockIdx.y;
    int g = blockIdx.x * blockDim.x + t;
    int i = g >> 5;
    int c = t & 31;
    float x = 0.f;
    if (i < NP) {
        int vid = g_vid[b * NP + i];
        if (vid < HW) {
            const float* p = pts + ((long)b * NP + i) * 3;
            float p0 = p[0], p1 = p[1], p2 = p[2];
            float inv = 1.0f / fmaxf((float)g_s.cnt[b * NSEG + vid], 1.0f);
            const float* sx = &g_s.sumxyz[((long)b * NSEG + vid) * 3];
            float m0 = sx[0] * inv, m1 = sx[1] * inv, m2 = sx[2] * inv;
            int cx = vid & 511, cy = vid >> 9;
            float cpx = -51.2f + ((float)cx + 0.5f) * 0.2f;
            float cpy = -51.2f + ((float)cy + 0.5f) * 0.2f;
            float f[9] = { p0, p1, p2, p0 - m0, p1 - m1, p2 - m2,
                           p0 - cpx, p1 - cpy, p2 };
#pragma unroll
            for (int k = 0; k < 9; k++) x += f[k] * w[k * 32 + c];
        }
        g_x1[((long)b * NP + i) * 32 + c] = x;
        atomicAdd(&ssum[c], x);
        atomicAdd(&ssq[c], x * x);
    }
    __syncthreads();
    if (t < 32) {
        int bk = blockIdx.x & (NBUCK - 1);
        atomicAdd(&g_s.bnb1[bk][b * 64 + t], (double)ssum[t]);
        atomicAdd(&g_s.bnb1[bk][b * 64 + 32 + t], (double)ssq[t]);
    }
}

// ---------------- BN finalize (reduce buckets) ----------------
__global__ void kBN(int which, const float* __restrict__ gam,
                    const float* __restrict__ bet) {
    int t = threadIdx.x;
    int C = which ? 64 : 32;
    int b = t / C, c = t % C;
    if (b >= BB) return;
    float nv = fmaxf((float)(NP - g_s.cnt[b * NSEG + HW]), 1.0f);
    double s = 0.0, sq = 0.0;
    if (which) {
        for (int k = 0; k < NBUCK; k++) {
            s += g_s.bnb2[k][b * 128 + c];
            sq += g_s.bnb2[k][b * 128 + 64 + c];
        }
    } else {
        for (int k = 0; k < NBUCK; k++) {
            s += g_s.bnb1[k][b * 64 + c];
            sq += g_s.bnb1[k][b * 64 + 32 + c];
        }
    }
    float mean = (float)(s / (double)nv);
    float var = (float)(sq / (double)nv) - mean * mean;
    var = fmaxf(var, 0.f);
    float sc = gam[c] * rsqrtf(var + 0.001f);
    float sh = bet[c] - mean * sc;
    if (which) { g_bn2ss[b * 128 + c] = sc; g_bn2ss[b * 128 + 64 + c] = sh; }
    else       { g_bn1ss[b * 64 + c] = sc;  g_bn1ss[b * 64 + 32 + c] = sh; }
}

// ---------------- kP1: CSR mix-pool1 (warp per voxel) ----------------
__global__ void kP1() {
    int b = blockIdx.y;
    int t = threadIdx.x;
    int w = t >> 5, lane = t & 31;
    int v = blockIdx.x * 8 + w;
    int base = b * NSEG + v;
    int cnt = g_s.cnt[base];
    if (cnt == 0) return;
    int end = g_start[base], beg = end - cnt;
    float sc = g_bn1ss[b * 64 + lane], sh = g_bn1ss[b * 64 + 32 + lane];
    float s = 0.f, m = 0.f;
    for (int j = beg; j < end; j++) {
        int pt = g_order[j];
        float x = g_x1[((long)b * NP + pt) * 32 + lane];
        float y = fmaxf(x * sc + sh, 0.f);
        s += y; m = fmaxf(m, y);
    }
    g_p1mix[((size_t)b * HW + v) * 32 + lane] = 0.5f * (m + s / (float)cnt);
}

// ---------------- kE: x1c @ W2 (raw), BN2 stats (bucketed) ----------------
__global__ void kE(const float* __restrict__ W2) {
    __shared__ float2 w[64 * 32];    // w[k*32+lane] = (W2[k][lane], W2[k][lane+32])
    __shared__ float ss[64], sq[64];
    int t = threadIdx.x, b = blockIdx.y;
    for (int k = t; k < 2048; k += 256) {
        int row = k >> 5, col = k & 31;
        w[k] = make_float2(W2[row * 64 + col], W2[row * 64 + 32 + col]);
    }
    if (t < 64) { ss[t] = 0.f; sq[t] = 0.f; }
    __syncthreads();
    int warp = t >> 5, lane = t & 31;
    int i = blockIdx.x * 8 + warp;
    if (i < NP) {
        int vid = g_vid[b * NP + i];
        float a0 = 0.f, a1 = 0.f;
        if (vid < HW) {
            float x = g_x1[((long)b * NP + i) * 32 + lane];
            float sc = g_bn1ss[b * 64 + lane], sh = g_bn1ss[b * 64 + 32 + lane];
            a0 = fmaxf(x * sc + sh, 0.f);
            a1 = g_p1mix[((size_t)b * HW + vid) * 32 + lane];
        }
        float olo = 0.f, ohi = 0.f;
#pragma unroll
        for (int k = 0; k < 32; k++) {
            float bk = __shfl_sync(0xffffffffu, a0, k);
            float2 wv = w[k * 32 + lane];
            olo += bk * wv.x;
            ohi += bk * wv.y;
        }
#pragma unroll
        for (int k = 0; k < 32; k++) {
            float bk = __shfl_sync(0xffffffffu, a1, k);
            float2 wv = w[(32 + k) * 32 + lane];
            olo += bk * wv.x;
            ohi += bk * wv.y;
        }
        size_t o2 = ((size_t)b * NP + i) * 64;
        g_x2[o2 + lane] = olo;
        g_x2[o2 + 32 + lane] = ohi;
        atomicAdd(&ss[lane], olo);
        atomicAdd(&ss[lane + 32], ohi);
        atomicAdd(&sq[lane], olo * olo);
        atomicAdd(&sq[lane + 32], ohi * ohi);
    }
    __syncthreads();
    if (t < 64) {
        int bk = blockIdx.x & (NBUCK - 1);
        atomicAdd(&g_s.bnb2[bk][b * 128 + t], (double)ss[t]);
        atomicAdd(&g_s.bnb2[bk][b * 128 + 64 + t], (double)sq[t]);
    }
}

// ---------------- kP2T: CSR mix-pool2 + transpose to [B,64,H,W] ----------------
__global__ void kP2T(float* __restrict__ out) {
    __shared__ float sT[64][33];
    int b = blockIdx.y, t = threadIdx.x;
    int vb = blockIdx.x * 32;
    int sub = t >> 6, c = t & 63;
    float sc = g_bn2ss[b * 128 + c], sh = g_bn2ss[b * 128 + 64 + c];
#pragma unroll
    for (int g8 = 0; g8 < 8; g8++) {
        int v = vb + g8 * 4 + sub;
        int base = b * NSEG + v;
        int cnt = g_s.cnt[base];
        float val = 0.f;
        if (cnt > 0) {
            int end = g_start[base], beg = end - cnt;
            float s = 0.f, m = 0.f;
            for (int j = beg; j < end; j++) {
                int pt = g_order[j];
                float x = g_x2[((size_t)b * NP + pt) * 64 + c];
                float y = fmaxf(x * sc + sh, 0.f);
                s += y; m = fmaxf(m, y);
            }
            val = 0.5f * (m + s / (float)cnt);
        }
        sT[c][g8 * 4 + sub] = val;
    }
    __syncthreads();
#pragma unroll
    for (int r = 0; r < 8; r++) {
        int j = t + 256 * r;
        int cc = j >> 5, v = j & 31;
        out[((size_t)b * 64 + cc) * HW + vb + v] = sT[cc][v];
    }
}

extern "C" void kernel_launch(void* const* d_in, const int* in_sizes, int n_in,
                              void* d_out, int out_size) {
    const float* pts = (const float*)d_in[0];
    const float* W1 = (const float*)d_in[1];
    const float* g1 = (const float*)d_in[2];
    const float* b1 = (const float*)d_in[3];
    const float* W2 = (const float*)d_in[4];
    const float* g2 = (const float*)d_in[5];
    const float* b2 = (const float*)d_in[6];
    float* out = (float*)d_out;

    void* sp = nullptr;
    cudaGetSymbolAddress(&sp, g_s);
    cudaMemsetAsync(sp, 0, sizeof(Scratch));

    dim3 gA((NP + 255) / 256, BB);
    kA<<<gA, 256>>>(pts);

    kS1<<<SCAN_NB, SCAN_B>>>();
    kS2<<<1, SCAN_B>>>();
    kS3<<<SCAN_NB, SCAN_B>>>();
    kSc<<<gA, 256>>>();

    dim3 gB((NP * 32 + 255) / 256, BB);
    kB<<<gB, 256>>>(pts, W1);

    kBN<<<1, BB * 32>>>(0, g1, b1);

    dim3 gP1(HW / 8, BB);
    kP1<<<gP1, 256>>>();

    dim3 gE((NP + 7) / 8, BB);
    kE<<<gE, 256>>>(W2);

    kBN<<<1, BB * 64>>>(1, g2, b2);

    dim3 gP2(HW / 32, BB);
    kP2T<<<gP2, 256>>>(out);
}

// round 7
// speedup vs baseline: 3.1196x; 1.5423x over previous
#include <cuda_runtime.h>
#include <cuda_bf16.h>
#include <math.h>

#define BB 2
#define NP 150000
#define NSLOT (BB * NP)
#define HW 262144
#define NSEG (HW + 1)
#define SCAN_N (BB * NSEG)
#define SCAN_B 1024
#define SCAN_NB ((SCAN_N + SCAN_B - 1) / SCAN_B)
#define NBUCK 128
#define ETILE 64
#define ETILES ((NSLOT + ETILE - 1) / ETILE)

struct Scratch {
    double bnb1[NBUCK][BB * 64];    // buckets: [b][ sum(32) | sumsq(32) ]
    double bnb2[NBUCK][BB * 128];   // buckets: [b][ sum(64) | sumsq(64) ]
    int    cnt[BB * NSEG];
    float  sumxyz[BB * NSEG * 3];
};

__device__ Scratch g_s;
__device__ int   g_start[SCAN_N];     // scan: exclusive start; after kB: end
__device__ int   g_bsum[SCAN_NB];
__device__ int   g_vid[BB * NP];      // per point
__device__ int   g_vids[NSLOT];       // per CSR slot: seg = b*NSEG+vid
__device__ float g_x1[(size_t)NSLOT * 32];       // CSR-ordered, raw (pre-BN)
__device__ float g_x2[(size_t)NSLOT * 64];       // CSR-ordered, raw (pre-BN)
__device__ float g_p1mix[(size_t)BB * HW * 32];  // occupied voxels only
__device__ float g_bn1ss[BB * 64];    // [b][ scale(32) | shift(32) ]
__device__ float g_bn2ss[BB * 128];   // [b][ scale(64) | shift(64) ]

// ---------------- kA: voxelize + counts + sum_xyz ----------------
__global__ void kA(const float* __restrict__ pts) {
    int b = blockIdx.y;
    int i = blockIdx.x * blockDim.x + threadIdx.x;
    if (i >= NP) return;
    const float* p = pts + ((long)b * NP + i) * 3;
    float p0 = p[0], p1 = p[1], p2 = p[2];
    float fx = floorf((p0 + 51.2f) / 0.2f);
    float fy = floorf((p1 + 51.2f) / 0.2f);
    float fz = floorf((p2 + 3.0f) / 6.0f);
    bool valid = (fx >= 0.f) && (fx < 512.f) && (fy >= 0.f) && (fy < 512.f) &&
                 (fz >= 0.f) && (fz < 1.f);
    int vid = HW;
    if (valid) {
        vid = (int)fy * 512 + (int)fx;
        float* sx = &g_s.sumxyz[((long)b * NSEG + vid) * 3];
        atomicAdd(sx + 0, p0);
        atomicAdd(sx + 1, p1);
        atomicAdd(sx + 2, p2);
    }
    atomicAdd(&g_s.cnt[b * NSEG + vid], 1);
    g_vid[b * NP + i] = vid;
}

// ---------------- scan ----------------
__device__ __forceinline__ int blockScanExcl(int v, int t, int* ws) {
    int lane = t & 31, w = t >> 5;
    int inc = v;
#pragma unroll
    for (int o = 1; o < 32; o <<= 1) {
        int n = __shfl_up_sync(0xffffffffu, inc, o);
        if (lane >= o) inc += n;
    }
    if (lane == 31) ws[w] = inc;
    __syncthreads();
    if (w == 0) {
        int s = ws[lane];
#pragma unroll
        for (int o = 1; o < 32; o <<= 1) {
            int n = __shfl_up_sync(0xffffffffu, s, o);
            if (lane >= o) s += n;
        }
        ws[lane] = s;
    }
    __syncthreads();
    return (w ? ws[w - 1] : 0) + inc - v;
}

__global__ void kS1() {
    __shared__ int ws[32];
    int t = threadIdx.x;
    int idx = blockIdx.x * SCAN_B + t;
    int v = (idx < SCAN_N) ? g_s.cnt[idx] : 0;
    int ex = blockScanExcl(v, t, ws);
    if (idx < SCAN_N) g_start[idx] = ex;
    if (t == 0) g_bsum[blockIdx.x] = ws[31];
}

__global__ void kS2() {
    __shared__ int ws[32];
    int t = threadIdx.x;
    int v = (t < SCAN_NB) ? g_bsum[t] : 0;
    int ex = blockScanExcl(v, t, ws);
    if (t < SCAN_NB) g_bsum[t] = ex;
}

__global__ void kS3() {
    int idx = blockIdx.x * SCAN_B + threadIdx.x;
    if (idx < SCAN_N) g_start[idx] += g_bsum[blockIdx.x];
}

// ------- kB: feats @ W1 -> x1[CSR slot], claim slot, BN1 stats -------
__global__ void kB(const float* __restrict__ pts, const float* __restrict__ W1) {
    __shared__ float w[9 * 32];
    __shared__ float ssum[32], ssq[32];
    int t = threadIdx.x;
    for (int k = t; k < 9 * 32; k += blockDim.x) w[k] = W1[k];
    if (t < 32) { ssum[t] = 0.f; ssq[t] = 0.f; }
    __syncthreads();
    int b = blockIdx.y;
    int g = blockIdx.x * blockDim.x + t;
    int i = g >> 5;
    int c = t & 31;
    int vid = g_vid[b * NP + i];
    int seg = b * NSEG + vid;
    int slot = 0;
    if (c == 0) slot = atomicAdd(&g_start[seg], 1);
    slot = __shfl_sync(0xffffffffu, slot, 0);
    float x = 0.f;
    if (vid < HW) {
        const float* p = pts + ((long)b * NP + i) * 3;
        float p0 = p[0], p1 = p[1], p2 = p[2];
        float inv = 1.0f / fmaxf((float)g_s.cnt[seg], 1.0f);
        const float* sx = &g_s.sumxyz[(long)seg * 3];
        float m0 = sx[0] * inv, m1 = sx[1] * inv, m2 = sx[2] * inv;
        int cx = vid & 511, cy = vid >> 9;
        float cpx = -51.2f + ((float)cx + 0.5f) * 0.2f;
        float cpy = -51.2f + ((float)cy + 0.5f) * 0.2f;
        float f[9] = { p0, p1, p2, p0 - m0, p1 - m1, p2 - m2,
                       p0 - cpx, p1 - cpy, p2 };
#pragma unroll
        for (int k = 0; k < 9; k++) x += f[k] * w[k * 32 + c];
    }
    g_x1[(size_t)slot * 32 + c] = x;
    if (c == 0) g_vids[slot] = seg;
    atomicAdd(&ssum[c], x);
    atomicAdd(&ssq[c], x * x);
    __syncthreads();
    if (t < 32) {
        int bk = blockIdx.x & (NBUCK - 1);
        atomicAdd(&g_s.bnb1[bk][b * 64 + t], (double)ssum[t]);
        atomicAdd(&g_s.bnb1[bk][b * 64 + 32 + t], (double)ssq[t]);
    }
}

// ---------------- BN finalize (reduce buckets) ----------------
__global__ void kBN(int which, const float* __restrict__ gam,
                    const float* __restrict__ bet) {
    int t = threadIdx.x;
    int C = which ? 64 : 32;
    int b = t / C, c = t % C;
    if (b >= BB) return;
    float nv = fmaxf((float)(NP - g_s.cnt[b * NSEG + HW]), 1.0f);
    double s = 0.0, sq = 0.0;
    if (which) {
        for (int k = 0; k < NBUCK; k++) {
            s += g_s.bnb2[k][b * 128 + c];
            sq += g_s.bnb2[k][b * 128 + 64 + c];
        }
    } else {
        for (int k = 0; k < NBUCK; k++) {
            s += g_s.bnb1[k][b * 64 + c];
            sq += g_s.bnb1[k][b * 64 + 32 + c];
        }
    }
    float mean = (float)(s / (double)nv);
    float var = (float)(sq / (double)nv) - mean * mean;
    var = fmaxf(var, 0.f);
    float sc = gam[c] * rsqrtf(var + 0.001f);
    float sh = bet[c] - mean * sc;
    if (which) { g_bn2ss[b * 128 + c] = sc; g_bn2ss[b * 128 + 64 + c] = sh; }
    else       { g_bn1ss[b * 64 + c] = sc;  g_bn1ss[b * 64 + 32 + c] = sh; }
}

// ---------------- kP1: CSR mix-pool1 (warp per voxel, contiguous rows) -----
__global__ void kP1() {
    int b = blockIdx.y;
    int t = threadIdx.x;
    int w = t >> 5, lane = t & 31;
    int v = blockIdx.x * 8 + w;
    int base = b * NSEG + v;
    int cnt = g_s.cnt[base];
    if (cnt == 0) return;
    int end = g_start[base], beg = end - cnt;
    float sc = g_bn1ss[b * 64 + lane], sh = g_bn1ss[b * 64 + 32 + lane];
    float s = 0.f, m = 0.f;
    for (int j = beg; j < end; j++) {
        float x = g_x1[(size_t)j * 32 + lane];
        float y = fmaxf(x * sc + sh, 0.f);
        s += y; m = fmaxf(m, y);
    }
    g_p1mix[((size_t)b * HW + v) * 32 + lane] = 0.5f * (m + s / (float)cnt);
}

// ------- kE: tiled GEMM [64 slots x 64 out x 64 k], BN2 stats -------
__global__ __launch_bounds__(256) void kE(const float* __restrict__ W2) {
    __shared__ float sA[ETILE * 65];
    __shared__ float sW[64 * 64];
    __shared__ int   sB[ETILE];
    __shared__ float ssb[2 * 64], sqb[2 * 64];
    int t = threadIdx.x;
    for (int idx = t; idx < 1024; idx += 256)
        ((float4*)sW)[idx] = ((const float4*)W2)[idx];
    if (t < 128) { ssb[t] = 0.f; sqb[t] = 0.f; }
    int warp = t >> 5, lane = t & 31;
    int tile = blockIdx.x;
#pragma unroll
    for (int r8 = 0; r8 < 8; r8++) {
        int row = warp * 8 + r8;
        int j = tile * ETILE + row;
        float a0 = 0.f, a1 = 0.f;
        int b = 0;
        if (j < NSLOT) {
            int seg = g_vids[j];
            b = (seg >= NSEG) ? 1 : 0;
            int vid = seg - b * NSEG;
            if (vid < HW) {
                float x = g_x1[(size_t)j * 32 + lane];
                float sc = g_bn1ss[b * 64 + lane], sh = g_bn1ss[b * 64 + 32 + lane];
                a0 = fmaxf(x * sc + sh, 0.f);
                a1 = g_p1mix[((size_t)b * HW + vid) * 32 + lane];
            }
        }
        sA[row * 65 + lane] = a0;
        sA[row * 65 + 32 + lane] = a1;
        if (lane == 0) sB[row] = b;
    }
    __syncthreads();

    int ty = t >> 4, tx = t & 15;     // 16x16 thread grid: 4 rows x 4 cols each
    float acc[4][4];
#pragma unroll
    for (int p = 0; p < 4; p++)
#pragma unroll
        for (int q = 0; q < 4; q++) acc[p][q] = 0.f;
    const float* Ar = &sA[(ty * 4) * 65];
#pragma unroll 8
    for (int k = 0; k < 64; k++) {
        float4 wv = *(const float4*)&sW[k * 64 + tx * 4];
#pragma unroll
        for (int p = 0; p < 4; p++) {
            float av = Ar[p * 65 + k];
            acc[p][0] += av * wv.x;
            acc[p][1] += av * wv.y;
            acc[p][2] += av * wv.z;
            acc[p][3] += av * wv.w;
        }
    }

    // write x2 (float4, coalesced) + per-thread stats split by batch
    float s0[4] = {0,0,0,0}, q0[4] = {0,0,0,0};
    float s1[4] = {0,0,0,0}, q1[4] = {0,0,0,0};
#pragma unroll
    for (int p = 0; p < 4; p++) {
        int row = ty * 4 + p;
        int j = tile * ETILE + row;
        if (j < NSLOT) {
            *(float4*)&g_x2[(size_t)j * 64 + tx * 4] =
                make_float4(acc[p][0], acc[p][1], acc[p][2], acc[p][3]);
            if (sB[row] == 0) {
#pragma unroll
                for (int q = 0; q < 4; q++) { s0[q] += acc[p][q]; q0[q] += acc[p][q] * acc[p][q]; }
            } else {
#pragma unroll
                for (int q = 0; q < 4; q++) { s1[q] += acc[p][q]; q1[q] += acc[p][q] * acc[p][q]; }
            }
        }
    }
#pragma unroll
    for (int q = 0; q < 4; q++) {
        atomicAdd(&ssb[tx * 4 + q], s0[q]);
        atomicAdd(&sqb[tx * 4 + q], q0[q]);
        atomicAdd(&ssb[64 + tx * 4 + q], s1[q]);
        atomicAdd(&sqb[64 + tx * 4 + q], q1[q]);
    }
    __syncthreads();
    if (t < 128) {
        int b = t >> 6, c = t & 63;
        int bk = blockIdx.x & (NBUCK - 1);
        atomicAdd(&g_s.bnb2[bk][b * 128 + c], (double)ssb[t]);
        atomicAdd(&g_s.bnb2[bk][b * 128 + 64 + c], (double)sqb[t]);
    }
}

// ------- kP2T: CSR mix-pool2 (contiguous rows) + transpose out -------
__global__ void kP2T(float* __restrict__ out) {
    __shared__ float sT[64][33];
    int b = blockIdx.y, t = threadIdx.x;
    int vb = blockIdx.x * 32;
    int sub = t >> 6, c = t & 63;
    float sc = g_bn2ss[b * 128 + c], sh = g_bn2ss[b * 128 + 64 + c];
#pragma unroll
    for (int g8 = 0; g8 < 8; g8++) {
        int v = vb + g8 * 4 + sub;
        int base = b * NSEG + v;
        int cnt = g_s.cnt[base];
        float val = 0.f;
        if (cnt > 0) {
            int end = g_start[base], beg = end - cnt;
            float s = 0.f, m = 0.f;
            for (int j = beg; j < end; j++) {
                float x = g_x2[(size_t)j * 64 + c];
                float y = fmaxf(x * sc + sh, 0.f);
                s += y; m = fmaxf(m, y);
            }
            val = 0.5f * (m + s / (float)cnt);
        }
        sT[c][g8 * 4 + sub] = val;
    }
    __syncthreads();
#pragma unroll
    for (int r = 0; r < 8; r++) {
        int j = t + 256 * r;
        int cc = j >> 5, v = j & 31;
        out[((size_t)b * 64 + cc) * HW + vb + v] = sT[cc][v];
    }
}

extern "C" void kernel_launch(void* const* d_in, const int* in_sizes, int n_in,
                              void* d_out, int out_size) {
    const float* pts = (const float*)d_in[0];
    const float* W1 = (const float*)d_in[1];
    const float* g1 = (const float*)d_in[2];
    const float* b1 = (const float*)d_in[3];
    const float* W2 = (const float*)d_in[4];
    const float* g2 = (const float*)d_in[5];
    const float* b2 = (const float*)d_in[6];
    float* out = (float*)d_out;

    void* sp = nullptr;
    cudaGetSymbolAddress(&sp, g_s);
    cudaMemsetAsync(sp, 0, sizeof(Scratch));

    dim3 gA((NP + 255) / 256, BB);
    kA<<<gA, 256>>>(pts);

    kS1<<<SCAN_NB, SCAN_B>>>();
    kS2<<<1, SCAN_B>>>();
    kS3<<<SCAN_NB, SCAN_B>>>();

    dim3 gB((NP * 32 + 255) / 256, BB);
    kB<<<gB, 256>>>(pts, W1);

    kBN<<<1, BB * 32>>>(0, g1, b1);

    dim3 gP1(HW / 8, BB);
    kP1<<<gP1, 256>>>();

    kE<<<ETILES, 256>>>(W2);

    kBN<<<1, BB * 64>>>(1, g2, b2);

    dim3 gP2(HW / 32, BB);
    kP2T<<<gP2, 256>>>(out);
}

// round 9
// speedup vs baseline: 3.2503x; 1.0419x over previous
#include <cuda_runtime.h>
#include <cuda_bf16.h>
#include <cuda_fp16.h>
#include <math.h>

#define BB 2
#define NP 150000
#define NSLOT (BB * NP)
#define HW 262144
#define NSEG (HW + 1)
#define SCAN_N (BB * NSEG)
#define SCAN_B 1024
#define SCAN_NB ((SCAN_N + SCAN_B - 1) / SCAN_B)
#define NBUCK 128
#define ETILE 64
#define ETILES ((NSLOT + ETILE - 1) / ETILE)

struct Scratch {
    double bnb1[NBUCK][BB * 64];    // buckets: [b][ sum(32) | sumsq(32) ]
    double bnb2[NBUCK][BB * 128];   // buckets: [b][ sum(64) | sumsq(64) ]
    int    cnt[BB * NSEG];
    float  sumxyz[BB * NSEG * 3];
};

__device__ Scratch g_s;
__device__ int    g_start[SCAN_N];    // scan: exclusive start; after kB: end
__device__ int    g_bsum[SCAN_NB];
__device__ int    g_vid[BB * NP];     // per point
__device__ int    g_vids[NSLOT];      // per CSR slot: seg = b*NSEG+vid
__device__ __half g_x1h[(size_t)NSLOT * 32];      // CSR-ordered, raw (pre-BN)
__device__ __half g_x2h[(size_t)NSLOT * 64];      // CSR-ordered, raw (pre-BN)
__device__ __half g_p1mixh[(size_t)BB * HW * 32]; // occupied voxels only
__device__ float  g_bn1ss[BB * 64];   // [b][ scale(32) | shift(32) ]
__device__ float  g_bn2ss[BB * 128];  // [b][ scale(64) | shift(64) ]

// ---- packed f32x2 helpers (Blackwell FFMA2) ----
__device__ __forceinline__ unsigned long long pack2(float lo, float hi) {
    unsigned long long r;
    asm("mov.b64 %0, {%1, %2};" : "=l"(r) : "f"(lo), "f"(hi));
    return r;
}
__device__ __forceinline__ void unpack2(unsigned long long v, float& lo, float& hi) {
    asm("mov.b64 {%0, %1}, %2;" : "=f"(lo), "=f"(hi) : "l"(v));
}
__device__ __forceinline__ void fma2(unsigned long long& acc, unsigned long long a,
                                     unsigned long long b) {
    asm("fma.rn.f32x2 %0, %1, %2, %0;" : "+l"(acc) : "l"(a), "l"(b));
}

// ---------------- kA: voxelize + counts + sum_xyz ----------------
__global__ void kA(const float* __restrict__ pts) {
    int b = blockIdx.y;
    int i = blockIdx.x * blockDim.x + threadIdx.x;
    if (i >= NP) return;
    const float* p = pts + ((long)b * NP + i) * 3;
    float p0 = p[0], p1 = p[1], p2 = p[2];
    float fx = floorf((p0 + 51.2f) / 0.2f);
    float fy = floorf((p1 + 51.2f) / 0.2f);
    float fz = floorf((p2 + 3.0f) / 6.0f);
    bool valid = (fx >= 0.f) && (fx < 512.f) && (fy >= 0.f) && (fy < 512.f) &&
                 (fz >= 0.f) && (fz < 1.f);
    int vid = HW;
    if (valid) {
        vid = (int)fy * 512 + (int)fx;
        float* sx = &g_s.sumxyz[((long)b * NSEG + vid) * 3];
        atomicAdd(sx + 0, p0);
        atomicAdd(sx + 1, p1);
        atomicAdd(sx + 2, p2);
    }
    atomicAdd(&g_s.cnt[b * NSEG + vid], 1);
    g_vid[b * NP + i] = vid;
}

// ---------------- scan ----------------
__device__ __forceinline__ int blockScanExcl(int v, int t, int* ws) {
    int lane = t & 31, w = t >> 5;
    int inc = v;
#pragma unroll
    for (int o = 1; o < 32; o <<= 1) {
        int n = __shfl_up_sync(0xffffffffu, inc, o);
        if (lane >= o) inc += n;
    }
    if (lane == 31) ws[w] = inc;
    __syncthreads();
    if (w == 0) {
        int s = ws[lane];
#pragma unroll
        for (int o = 1; o < 32; o <<= 1) {
            int n = __shfl_up_sync(0xffffffffu, s, o);
            if (lane >= o) s += n;
        }
        ws[lane] = s;
    }
    __syncthreads();
    return (w ? ws[w - 1] : 0) + inc - v;
}

__global__ void kS1() {
    __shared__ int ws[32];
    int t = threadIdx.x;
    int idx = blockIdx.x * SCAN_B + t;
    int v = (idx < SCAN_N) ? g_s.cnt[idx] : 0;
    int ex = blockScanExcl(v, t, ws);
    if (idx < SCAN_N) g_start[idx] = ex;
    if (t == 0) g_bsum[blockIdx.x] = ws[31];
}

__global__ void kS2() {
    __shared__ int ws[32];
    int t = threadIdx.x;
    int v = (t < SCAN_NB) ? g_bsum[t] : 0;
    int ex = blockScanExcl(v, t, ws);
    if (t < SCAN_NB) g_bsum[t] = ex;
}

__global__ void kS3() {
    int idx = blockIdx.x * SCAN_B + threadIdx.x;
    if (idx < SCAN_N) g_start[idx] += g_bsum[blockIdx.x];
}

// ------- kB: feats @ W1 -> x1[CSR slot], claim slot, BN1 stats -------
__global__ void kB(const float* __restrict__ pts, const float* __restrict__ W1) {
    __shared__ float w[9 * 32];
    __shared__ float ssum[32], ssq[32];
    int t = threadIdx.x;
    for (int k = t; k < 9 * 32; k += blockDim.x) w[k] = W1[k];
    if (t < 32) { ssum[t] = 0.f; ssq[t] = 0.f; }
    __syncthreads();
    int b = blockIdx.y;
    int g = blockIdx.x * blockDim.x + t;
    int i = g >> 5;
    int c = t & 31;
    int vid = g_vid[b * NP + i];
    int seg = b * NSEG + vid;
    int slot = 0;
    if (c == 0) slot = atomicAdd(&g_start[seg], 1);
    slot = __shfl_sync(0xffffffffu, slot, 0);
    float x = 0.f;
    if (vid < HW) {
        const float* p = pts + ((long)b * NP + i) * 3;
        float p0 = p[0], p1 = p[1], p2 = p[2];
        float inv = 1.0f / fmaxf((float)g_s.cnt[seg], 1.0f);
        const float* sx = &g_s.sumxyz[(long)seg * 3];
        float m0 = sx[0] * inv, m1 = sx[1] * inv, m2 = sx[2] * inv;
        int cx = vid & 511, cy = vid >> 9;
        float cpx = -51.2f + ((float)cx + 0.5f) * 0.2f;
        float cpy = -51.2f + ((float)cy + 0.5f) * 0.2f;
        float f[9] = { p0, p1, p2, p0 - m0, p1 - m1, p2 - m2,
                       p0 - cpx, p1 - cpy, p2 };
#pragma unroll
        for (int k = 0; k < 9; k++) x += f[k] * w[k * 32 + c];
    }
    g_x1h[(size_t)slot * 32 + c] = __float2half(x);
    if (c == 0) g_vids[slot] = seg;
    atomicAdd(&ssum[c], x);
    atomicAdd(&ssq[c], x * x);
    __syncthreads();
    if (t < 32) {
        int bk = blockIdx.x & (NBUCK - 1);
        atomicAdd(&g_s.bnb1[bk][b * 64 + t], (double)ssum[t]);
        atomicAdd(&g_s.bnb1[bk][b * 64 + 32 + t], (double)ssq[t]);
    }
}

// ---------------- BN finalize (reduce buckets) ----------------
__global__ void kBN(int which, const float* __restrict__ gam,
                    const float* __restrict__ bet) {
    int t = threadIdx.x;
    int C = which ? 64 : 32;
    int b = t / C, c = t % C;
    if (b >= BB) return;
    float nv = fmaxf((float)(NP - g_s.cnt[b * NSEG + HW]), 1.0f);
    double s = 0.0, sq = 0.0;
    if (which) {
        for (int k = 0; k < NBUCK; k++) {
            s += g_s.bnb2[k][b * 128 + c];
            sq += g_s.bnb2[k][b * 128 + 64 + c];
        }
    } else {
        for (int k = 0; k < NBUCK; k++) {
            s += g_s.bnb1[k][b * 64 + c];
            sq += g_s.bnb1[k][b * 64 + 32 + c];
        }
    }
    float mean = (float)(s / (double)nv);
    float var = (float)(sq / (double)nv) - mean * mean;
    var = fmaxf(var, 0.f);
    float sc = gam[c] * rsqrtf(var + 0.001f);
    float sh = bet[c] - mean * sc;
    if (which) { g_bn2ss[b * 128 + c] = sc; g_bn2ss[b * 128 + 64 + c] = sh; }
    else       { g_bn1ss[b * 64 + c] = sc;  g_bn1ss[b * 64 + 32 + c] = sh; }
}

// ---------------- kP1: CSR mix-pool1 (warp per voxel, contiguous rows) -----
__global__ void kP1() {
    int b = blockIdx.y;
    int t = threadIdx.x;
    int w = t >> 5, lane = t & 31;
    int v = blockIdx.x * 8 + w;
    int base = b * NSEG + v;
    int cnt = g_s.cnt[base];
    if (cnt == 0) return;
    int end = g_start[base], beg = end - cnt;
    float sc = g_bn1ss[b * 64 + lane], sh = g_bn1ss[b * 64 + 32 + lane];
    float s = 0.f, m = 0.f;
    for (int j = beg; j < end; j++) {
        float x = __half2float(g_x1h[(size_t)j * 32 + lane]);
        float y = fmaxf(x * sc + sh, 0.f);
        s += y; m = fmaxf(m, y);
    }
    g_p1mixh[((size_t)b * HW + v) * 32 + lane] =
        __float2half(0.5f * (m + s / (float)cnt));
}

// ------- kE: tiled GEMM [64 slots x 64 out x 64 k], f32x2 FMA, BN2 stats ---
__global__ __launch_bounds__(256) void kE(const float* __restrict__ W2) {
    __shared__ float sA[ETILE * 65];
    __shared__ float sW[64 * 64];
    __shared__ int   sB[ETILE];
    __shared__ float ssb[2 * 64], sqb[2 * 64];
    int t = threadIdx.x;
    for (int idx = t; idx < 1024; idx += 256)
        ((float4*)sW)[idx] = ((const float4*)W2)[idx];
    if (t < 128) { ssb[t] = 0.f; sqb[t] = 0.f; }
    int warp = t >> 5, lane = t & 31;
    int tile = blockIdx.x;
#pragma unroll
    for (int r8 = 0; r8 < 8; r8++) {
        int row = warp * 8 + r8;
        int j = tile * ETILE + row;
        float a0 = 0.f, a1 = 0.f;
        int b = 0;
        if (j < NSLOT) {
            int seg = g_vids[j];
            b = (seg >= NSEG) ? 1 : 0;
            int vid = seg - b * NSEG;
            if (vid < HW) {
                float x = __half2float(g_x1h[(size_t)j * 32 + lane]);
                float sc = g_bn1ss[b * 64 + lane], sh = g_bn1ss[b * 64 + 32 + lane];
                a0 = fmaxf(x * sc + sh, 0.f);
                a1 = __half2float(g_p1mixh[((size_t)b * HW + vid) * 32 + lane]);
            }
        }
        sA[row * 65 + lane] = a0;
        sA[row * 65 + 32 + lane] = a1;
        if (lane == 0) sB[row] = b;
    }
    __syncthreads();

    int ty = t >> 4, tx = t & 15;     // 16x16 thread grid: 4 rows x 4 cols each
    unsigned long long acc01[4], acc23[4];
#pragma unroll
    for (int p = 0; p < 4; p++) { acc01[p] = pack2(0.f, 0.f); acc23[p] = pack2(0.f, 0.f); }
    const float* Ar = &sA[(ty * 4) * 65];
#pragma unroll 8
    for (int k = 0; k < 64; k++) {
        float4 wv = *(const float4*)&sW[k * 64 + tx * 4];
        unsigned long long w01 = pack2(wv.x, wv.y);
        unsigned long long w23 = pack2(wv.z, wv.w);
#pragma unroll
        for (int p = 0; p < 4; p++) {
            float av = Ar[p * 65 + k];
            unsigned long long a2 = pack2(av, av);
            fma2(acc01[p], a2, w01);
            fma2(acc23[p], a2, w23);
        }
    }

    // write x2 (half2 pairs) + per-thread stats split by batch
    float s0[4] = {0,0,0,0}, q0[4] = {0,0,0,0};
    float s1[4] = {0,0,0,0}, q1[4] = {0,0,0,0};
#pragma unroll
    for (int p = 0; p < 4; p++) {
        int row = ty * 4 + p;
        int j = tile * ETILE + row;
        if (j < NSLOT) {
            float a, bq, cq, dq;
            unpack2(acc01[p], a, bq);
            unpack2(acc23[p], cq, dq);
            __half2* dst = (__half2*)&g_x2h[(size_t)j * 64 + tx * 4];
            dst[0] = __floats2half2_rn(a, bq);
            dst[1] = __floats2half2_rn(cq, dq);
            float vv[4] = { a, bq, cq, dq };
            if (sB[row] == 0) {
#pragma unroll
                for (int q = 0; q < 4; q++) { s0[q] += vv[q]; q0[q] += vv[q] * vv[q]; }
            } else {
#pragma unroll
                for (int q = 0; q < 4; q++) { s1[q] += vv[q]; q1[q] += vv[q] * vv[q]; }
            }
        }
    }
#pragma unroll
    for (int q = 0; q < 4; q++) {
        atomicAdd(&ssb[tx * 4 + q], s0[q]);
        atomicAdd(&sqb[tx * 4 + q], q0[q]);
        atomicAdd(&ssb[64 + tx * 4 + q], s1[q]);
        atomicAdd(&sqb[64 + tx * 4 + q], q1[q]);
    }
    __syncthreads();
    if (t < 128) {
        int b = t >> 6, c = t & 63;
        int bk = blockIdx.x & (NBUCK - 1);
        atomicAdd(&g_s.bnb2[bk][b * 128 + c], (double)ssb[t]);
        atomicAdd(&g_s.bnb2[bk][b * 128 + 64 + c], (double)sqb[t]);
    }
}

// ------- kP2T: CSR mix-pool2 (contiguous rows) + transpose out -------
__global__ void kP2T(float* __restrict__ out) {
    __shared__ float sT[64][33];
    int b = blockIdx.y, t = threadIdx.x;
    int vb = blockIdx.x * 32;
    int sub = t >> 6, c = t & 63;
    float sc = g_bn2ss[b * 128 + c], sh = g_bn2ss[b * 128 + 64 + c];
#pragma unroll
    for (int g8 = 0; g8 < 8; g8++) {
        int v = vb + g8 * 4 + sub;
        int base = b * NSEG + v;
        int cnt = g_s.cnt[base];
        float val = 0.f;
        if (cnt > 0) {
            int end = g_start[base], beg = end - cnt;
            float s = 0.f, m = 0.f;
            for (int j = beg; j < end; j++) {
                float x = __half2float(g_x2h[(size_t)j * 64 + c]);
                float y = fmaxf(x * sc + sh, 0.f);
                s += y; m = fmaxf(m, y);
            }
            val = 0.5f * (m + s / (float)cnt);
        }
        sT[c][g8 * 4 + sub] = val;
    }
    __syncthreads();
#pragma unroll
    for (int r = 0; r < 8; r++) {
        int j = t + 256 * r;
        int cc = j >> 5, v = j & 31;
        out[((size_t)b * 64 + cc) * HW + vb + v] = sT[cc][v];
    }
}

extern "C" void kernel_launch(void* const* d_in, const int* in_sizes, int n_in,
                              void* d_out, int out_size) {
    const float* pts = (const float*)d_in[0];
    const float* W1 = (const float*)d_in[1];
    const float* g1 = (const float*)d_in[2];
    const float* b1 = (const float*)d_in[3];
    const float* W2 = (const float*)d_in[4];
    const float* g2 = (const float*)d_in[5];
    const float* b2 = (const float*)d_in[6];
    float* out = (float*)d_out;

    void* sp = nullptr;
    cudaGetSymbolAddress(&sp, g_s);
    cudaMemsetAsync(sp, 0, sizeof(Scratch));

    dim3 gA((NP + 255) / 256, BB);
    kA<<<gA, 256>>>(pts);

    kS1<<<SCAN_NB, SCAN_B>>>();
    kS2<<<1, SCAN_B>>>();
    kS3<<<SCAN_NB, SCAN_B>>>();

    dim3 gB((NP * 32 + 255) / 256, BB);
    kB<<<gB, 256>>>(pts, W1);

    kBN<<<1, BB * 32>>>(0, g1, b1);

    dim3 gP1(HW / 8, BB);
    kP1<<<gP1, 256>>>();

    kE<<<ETILES, 256>>>(W2);

    kBN<<<1, BB * 64>>>(1, g2, b2);

    dim3 gP2(HW / 32, BB);
    kP2T<<<gP2, 256>>>(out);
}

// round 10
// speedup vs baseline: 3.5003x; 1.0769x over previous
#include <cuda_runtime.h>
#include <cuda_bf16.h>
#include <cuda_fp16.h>
#include <math.h>

#define BB 2
#define NP 150000
#define NSLOT (BB * NP)
#define HW 262144
#define NSEG (HW + 1)
#define SCAN_N (BB * NSEG)
#define SCAN_B 1024
#define SCAN_NB ((SCAN_N + SCAN_B - 1) / SCAN_B)
#define NBUCK 128
#define ETILE 64
#define ETILES ((NSLOT + ETILE - 1) / ETILE)

struct Scratch {
    double bnb1[NBUCK][BB * 64];    // buckets: [b][ sum(32) | sumsq(32) ]
    double bnb2[NBUCK][BB * 128];   // buckets: [b][ sum(64) | sumsq(64) ]
    int    cnt[BB * NSEG];
    float  sumxyz[BB * NSEG * 3];
};

__device__ Scratch g_s;
__device__ int    g_start[SCAN_N];    // scan: exclusive start; after kB: end
__device__ int    g_bsum[SCAN_NB];
__device__ int    g_vid[BB * NP];     // per point
__device__ int    g_vids[NSLOT];      // per CSR slot: seg = b*NSEG+vid
__device__ __half g_x1h[(size_t)NSLOT * 32];      // CSR-ordered, raw (pre-BN)
__device__ __half g_x2h[(size_t)NSLOT * 64];      // CSR-ordered, raw (pre-BN)
__device__ __half g_p1mixh[(size_t)BB * HW * 32]; // occupied voxels only
__device__ float  g_bn1ss[BB * 64];   // [b][ scale(32) | shift(32) ]
__device__ float  g_bn2ss[BB * 128];  // [b][ scale(64) | shift(64) ]

// ---- packed f32x2 helpers (Blackwell FFMA2) ----
__device__ __forceinline__ unsigned long long pack2(float lo, float hi) {
    unsigned long long r;
    asm("mov.b64 %0, {%1, %2};" : "=l"(r) : "f"(lo), "f"(hi));
    return r;
}
__device__ __forceinline__ void unpack2(unsigned long long v, float& lo, float& hi) {
    asm("mov.b64 {%0, %1}, %2;" : "=f"(lo), "=f"(hi) : "l"(v));
}
__device__ __forceinline__ void fma2(unsigned long long& acc, unsigned long long a,
                                     unsigned long long b) {
    asm("fma.rn.f32x2 %0, %1, %2, %0;" : "+l"(acc) : "l"(a), "l"(b));
}

// ---------------- kA: voxelize + counts + sum_xyz ----------------
__global__ void kA(const float* __restrict__ pts) {
    int b = blockIdx.y;
    int i = blockIdx.x * blockDim.x + threadIdx.x;
    if (i >= NP) return;
    const float* p = pts + ((long)b * NP + i) * 3;
    float p0 = p[0], p1 = p[1], p2 = p[2];
    float fx = floorf((p0 + 51.2f) / 0.2f);
    float fy = floorf((p1 + 51.2f) / 0.2f);
    float fz = floorf((p2 + 3.0f) / 6.0f);
    bool valid = (fx >= 0.f) && (fx < 512.f) && (fy >= 0.f) && (fy < 512.f) &&
                 (fz >= 0.f) && (fz < 1.f);
    int vid = HW;
    if (valid) {
        vid = (int)fy * 512 + (int)fx;
        float* sx = &g_s.sumxyz[((long)b * NSEG + vid) * 3];
        atomicAdd(sx + 0, p0);
        atomicAdd(sx + 1, p1);
        atomicAdd(sx + 2, p2);
    }
    atomicAdd(&g_s.cnt[b * NSEG + vid], 1);
    g_vid[b * NP + i] = vid;
}

// ---------------- scan ----------------
__device__ __forceinline__ int blockScanExcl(int v, int t, int* ws) {
    int lane = t & 31, w = t >> 5;
    int inc = v;
#pragma unroll
    for (int o = 1; o < 32; o <<= 1) {
        int n = __shfl_up_sync(0xffffffffu, inc, o);
        if (lane >= o) inc += n;
    }
    if (lane == 31) ws[w] = inc;
    __syncthreads();
    if (w == 0) {
        int s = ws[lane];
#pragma unroll
        for (int o = 1; o < 32; o <<= 1) {
            int n = __shfl_up_sync(0xffffffffu, s, o);
            if (lane >= o) s += n;
        }
        ws[lane] = s;
    }
    __syncthreads();
    return (w ? ws[w - 1] : 0) + inc - v;
}

__global__ void kS1() {
    __shared__ int ws[32];
    int t = threadIdx.x;
    int idx = blockIdx.x * SCAN_B + t;
    int v = (idx < SCAN_N) ? g_s.cnt[idx] : 0;
    int ex = blockScanExcl(v, t, ws);
    if (idx < SCAN_N) g_start[idx] = ex;
    if (t == 0) g_bsum[blockIdx.x] = ws[31];
}

__global__ void kS2() {
    __shared__ int ws[32];
    int t = threadIdx.x;
    int v = (t < SCAN_NB) ? g_bsum[t] : 0;
    int ex = blockScanExcl(v, t, ws);
    if (t < SCAN_NB) g_bsum[t] = ex;
}

__global__ void kS3() {
    int idx = blockIdx.x * SCAN_B + threadIdx.x;
    if (idx < SCAN_N) g_start[idx] += g_bsum[blockIdx.x];
}

// ------- kB: feats @ W1 -> x1[CSR slot]; 8 points/warp, reg-accum stats -----
__global__ void kB(const float* __restrict__ pts, const float* __restrict__ W1) {
    __shared__ float w[9 * 32];
    __shared__ float ssum[32], ssq[32];
    int t = threadIdx.x;
    for (int k = t; k < 9 * 32; k += blockDim.x) w[k] = W1[k];
    if (t < 32) { ssum[t] = 0.f; ssq[t] = 0.f; }
    __syncthreads();
    int b = blockIdx.y;
    int warp = t >> 5, c = t & 31;
    int i0 = blockIdx.x * 64 + warp * 8;
    float lsum = 0.f, lsq = 0.f;
#pragma unroll
    for (int r = 0; r < 8; r++) {
        int i = i0 + r;
        if (i >= NP) break;
        int vid = g_vid[b * NP + i];
        int seg = b * NSEG + vid;
        int slot = 0;
        if (c == 0) slot = atomicAdd(&g_start[seg], 1);
        slot = __shfl_sync(0xffffffffu, slot, 0);
        float x = 0.f;
        if (vid < HW) {
            const float* p = pts + ((long)b * NP + i) * 3;
            float p0 = p[0], p1 = p[1], p2 = p[2];
            float inv = 1.0f / fmaxf((float)g_s.cnt[seg], 1.0f);
            const float* sx = &g_s.sumxyz[(long)seg * 3];
            float m0 = sx[0] * inv, m1 = sx[1] * inv, m2 = sx[2] * inv;
            int cx = vid & 511, cy = vid >> 9;
            float cpx = -51.2f + ((float)cx + 0.5f) * 0.2f;
            float cpy = -51.2f + ((float)cy + 0.5f) * 0.2f;
            float f[9] = { p0, p1, p2, p0 - m0, p1 - m1, p2 - m2,
                           p0 - cpx, p1 - cpy, p2 };
#pragma unroll
            for (int k = 0; k < 9; k++) x += f[k] * w[k * 32 + c];
        }
        g_x1h[(size_t)slot * 32 + c] = __float2half(x);
        if (c == 0) g_vids[slot] = seg;
        lsum += x; lsq += x * x;
    }
    atomicAdd(&ssum[c], lsum);
    atomicAdd(&ssq[c], lsq);
    __syncthreads();
    if (t < 32) {
        int bk = blockIdx.x & (NBUCK - 1);
        atomicAdd(&g_s.bnb1[bk][b * 64 + t], (double)ssum[t]);
        atomicAdd(&g_s.bnb1[bk][b * 64 + 32 + t], (double)ssq[t]);
    }
}

// ---------------- BN finalize (reduce buckets) ----------------
__global__ void kBN(int which, const float* __restrict__ gam,
                    const float* __restrict__ bet) {
    int t = threadIdx.x;
    int C = which ? 64 : 32;
    int b = t / C, c = t % C;
    if (b >= BB) return;
    float nv = fmaxf((float)(NP - g_s.cnt[b * NSEG + HW]), 1.0f);
    double s = 0.0, sq = 0.0;
    if (which) {
        for (int k = 0; k < NBUCK; k++) {
            s += g_s.bnb2[k][b * 128 + c];
            sq += g_s.bnb2[k][b * 128 + 64 + c];
        }
    } else {
        for (int k = 0; k < NBUCK; k++) {
            s += g_s.bnb1[k][b * 64 + c];
            sq += g_s.bnb1[k][b * 64 + 32 + c];
        }
    }
    float mean = (float)(s / (double)nv);
    float var = (float)(sq / (double)nv) - mean * mean;
    var = fmaxf(var, 0.f);
    float sc = gam[c] * rsqrtf(var + 0.001f);
    float sh = bet[c] - mean * sc;
    if (which) { g_bn2ss[b * 128 + c] = sc; g_bn2ss[b * 128 + 64 + c] = sh; }
    else       { g_bn1ss[b * 64 + c] = sc;  g_bn1ss[b * 64 + 32 + c] = sh; }
}

// ---------------- kP1: CSR mix-pool1 (warp per voxel, contiguous rows) -----
__global__ void kP1() {
    int b = blockIdx.y;
    int t = threadIdx.x;
    int w = t >> 5, lane = t & 31;
    int v = blockIdx.x * 8 + w;
    int base = b * NSEG + v;
    int cnt = g_s.cnt[base];
    if (cnt == 0) return;
    int end = g_start[base], beg = end - cnt;
    float sc = g_bn1ss[b * 64 + lane], sh = g_bn1ss[b * 64 + 32 + lane];
    float s = 0.f, m = 0.f;
    for (int j = beg; j < end; j++) {
        float x = __half2float(g_x1h[(size_t)j * 32 + lane]);
        float y = fmaxf(x * sc + sh, 0.f);
        s += y; m = fmaxf(m, y);
    }
    g_p1mixh[((size_t)b * HW + v) * 32 + lane] =
        __float2half(0.5f * (m + s / (float)cnt));
}

// ------- kE: tiled GEMM [64 slots x 64 out x 64 k], f32x2 FMA, BN2 stats ---
__global__ __launch_bounds__(256) void kE(const float* __restrict__ W2) {
    __shared__ float sA[ETILE * 65];
    __shared__ float sW[64 * 64];
    __shared__ int   sB[ETILE];
    __shared__ float ssb[2 * 64], sqb[2 * 64];
    int t = threadIdx.x;
    for (int idx = t; idx < 1024; idx += 256)
        ((float4*)sW)[idx] = ((const float4*)W2)[idx];
    if (t < 128) { ssb[t] = 0.f; sqb[t] = 0.f; }
    int warp = t >> 5, lane = t & 31;
    int tile = blockIdx.x;
#pragma unroll
    for (int r8 = 0; r8 < 8; r8++) {
        int row = warp * 8 + r8;
        int j = tile * ETILE + row;
        float a0 = 0.f, a1 = 0.f;
        int b = 0;
        if (j < NSLOT) {
            int seg = g_vids[j];
            b = (seg >= NSEG) ? 1 : 0;
            int vid = seg - b * NSEG;
            if (vid < HW) {
                float x = __half2float(g_x1h[(size_t)j * 32 + lane]);
                float sc = g_bn1ss[b * 64 + lane], sh = g_bn1ss[b * 64 + 32 + lane];
                a0 = fmaxf(x * sc + sh, 0.f);
                a1 = __half2float(g_p1mixh[((size_t)b * HW + vid) * 32 + lane]);
            }
        }
        sA[row * 65 + lane] = a0;
        sA[row * 65 + 32 + lane] = a1;
        if (lane == 0) sB[row] = b;
    }
    __syncthreads();

    int ty = t >> 4, tx = t & 15;     // 16x16 thread grid: 4 rows x 4 cols each
    unsigned long long acc01[4], acc23[4];
#pragma unroll
    for (int p = 0; p < 4; p++) { acc01[p] = pack2(0.f, 0.f); acc23[p] = pack2(0.f, 0.f); }
    const float* Ar = &sA[(ty * 4) * 65];
#pragma unroll 8
    for (int k = 0; k < 64; k++) {
        float4 wv = *(const float4*)&sW[k * 64 + tx * 4];
        unsigned long long w01 = pack2(wv.x, wv.y);
        unsigned long long w23 = pack2(wv.z, wv.w);
#pragma unroll
        for (int p = 0; p < 4; p++) {
            float av = Ar[p * 65 + k];
            unsigned long long a2 = pack2(av, av);
            fma2(acc01[p], a2, w01);
            fma2(acc23[p], a2, w23);
        }
    }

    // write x2 (half2 pairs) + per-thread stats split by batch
    float s0[4] = {0,0,0,0}, q0[4] = {0,0,0,0};
    float s1[4] = {0,0,0,0}, q1[4] = {0,0,0,0};
#pragma unroll
    for (int p = 0; p < 4; p++) {
        int row = ty * 4 + p;
        int j = tile * ETILE + row;
        if (j < NSLOT) {
            float a, bq, cq, dq;
            unpack2(acc01[p], a, bq);
            unpack2(acc23[p], cq, dq);
            __half2* dst = (__half2*)&g_x2h[(size_t)j * 64 + tx * 4];
            dst[0] = __floats2half2_rn(a, bq);
            dst[1] = __floats2half2_rn(cq, dq);
            float vv[4] = { a, bq, cq, dq };
            if (sB[row] == 0) {
#pragma unroll
                for (int q = 0; q < 4; q++) { s0[q] += vv[q]; q0[q] += vv[q] * vv[q]; }
            } else {
#pragma unroll
                for (int q = 0; q < 4; q++) { s1[q] += vv[q]; q1[q] += vv[q] * vv[q]; }
            }
        }
    }
#pragma unroll
    for (int q = 0; q < 4; q++) {
        atomicAdd(&ssb[tx * 4 + q], s0[q]);
        atomicAdd(&sqb[tx * 4 + q], q0[q]);
        atomicAdd(&ssb[64 + tx * 4 + q], s1[q]);
        atomicAdd(&sqb[64 + tx * 4 + q], q1[q]);
    }
    __syncthreads();
    if (t < 128) {
        int b = t >> 6, c = t & 63;
        int bk = blockIdx.x & (NBUCK - 1);
        atomicAdd(&g_s.bnb2[bk][b * 128 + c], (double)ssb[t]);
        atomicAdd(&g_s.bnb2[bk][b * 128 + 64 + c], (double)sqb[t]);
    }
}

// ------- kP2T: CSR mix-pool2 (contiguous rows) + transpose out -------
__global__ void kP2T(float* __restrict__ out) {
    __shared__ float sT[64][33];
    int b = blockIdx.y, t = threadIdx.x;
    int vb = blockIdx.x * 32;
    int sub = t >> 6, c = t & 63;
    float sc = g_bn2ss[b * 128 + c], sh = g_bn2ss[b * 128 + 64 + c];
#pragma unroll
    for (int g8 = 0; g8 < 8; g8++) {
        int v = vb + g8 * 4 + sub;
        int base = b * NSEG + v;
        int cnt = g_s.cnt[base];
        float val = 0.f;
        if (cnt > 0) {
            int end = g_start[base], beg = end - cnt;
            float s = 0.f, m = 0.f;
            for (int j = beg; j < end; j++) {
                float x = __half2float(g_x2h[(size_t)j * 64 + c]);
                float y = fmaxf(x * sc + sh, 0.f);
                s += y; m = fmaxf(m, y);
            }
            val = 0.5f * (m + s / (float)cnt);
        }
        sT[c][g8 * 4 + sub] = val;
    }
    __syncthreads();
#pragma unroll
    for (int r = 0; r < 8; r++) {
        int j = t + 256 * r;
        int cc = j >> 5, v = j & 31;
        out[((size_t)b * 64 + cc) * HW + vb + v] = sT[cc][v];
    }
}

extern "C" void kernel_launch(void* const* d_in, const int* in_sizes, int n_in,
                              void* d_out, int out_size) {
    const float* pts = (const float*)d_in[0];
    const float* W1 = (const float*)d_in[1];
    const float* g1 = (const float*)d_in[2];
    const float* b1 = (const float*)d_in[3];
    const float* W2 = (const float*)d_in[4];
    const float* g2 = (const float*)d_in[5];
    const float* b2 = (const float*)d_in[6];
    float* out = (float*)d_out;

    void* sp = nullptr;
    cudaGetSymbolAddress(&sp, g_s);
    cudaMemsetAsync(sp, 0, sizeof(Scratch));

    dim3 gA((NP + 255) / 256, BB);
    kA<<<gA, 256>>>(pts);

    kS1<<<SCAN_NB, SCAN_B>>>();
    kS2<<<1, SCAN_B>>>();
    kS3<<<SCAN_NB, SCAN_B>>>();

    dim3 gB((NP + 63) / 64, BB);
    kB<<<gB, 256>>>(pts, W1);

    kBN<<<1, BB * 32>>>(0, g1, b1);

    dim3 gP1(HW / 8, BB);
    kP1<<<gP1, 256>>>();

    kE<<<ETILES, 256>>>(W2);

    kBN<<<1, BB * 64>>>(1, g2, b2);

    dim3 gP2(HW / 32, BB);
    kP2T<<<gP2, 256>>>(out);
}

// round 12
// speedup vs baseline: 3.6456x; 1.0415x over previous
#include <cuda_runtime.h>
#include <cuda_bf16.h>
#include <cuda_fp16.h>
#include <math.h>

#define BB 2
#define NP 150000
#define NSLOT (BB * NP)
#define HW 262144
#define NSEG (HW + 1)
#define SCAN_N (BB * NSEG)
#define SCAN_B 1024
#define SCAN_NB ((SCAN_N + SCAN_B - 1) / SCAN_B)
#define NBUCK 128
#define ETILE 64
#define ETILES ((NSLOT + ETILE - 1) / ETILE)

struct Scratch {
    double bnb1[NBUCK][BB * 64];    // buckets: [b][ sum(32) | sumsq(32) ]
    double bnb2[NBUCK][BB * 128];   // buckets: [b][ sum(64) | sumsq(64) ]
    float4 pc[BB * NSEG];           // {sum_x, sum_y, sum_z, count}
};

__device__ Scratch g_s;
__device__ int    g_start[SCAN_N];    // local-block exclusive scan; after kB: local end
__device__ int    g_bsum[SCAN_NB];    // exclusive scan of block sums
__device__ int    g_vid[BB * NP];     // per point
__device__ int    g_vids[NSLOT];      // per CSR slot: seg = b*NSEG+vid
__device__ __half g_x1h[(size_t)NSLOT * 32];      // CSR-ordered, raw (pre-BN)
__device__ __half g_x2h[(size_t)NSLOT * 64];      // CSR-ordered, raw (pre-BN)
__device__ __half g_p1mixh[(size_t)BB * HW * 32]; // occupied voxels only
__device__ float  g_bn1ss[BB * 64];   // [b][ scale(32) | shift(32) ]
__device__ float  g_bn2ss[BB * 128];  // [b][ scale(64) | shift(64) ]

// ---- packed f32x2 helpers (Blackwell FFMA2) ----
__device__ __forceinline__ unsigned long long pack2(float lo, float hi) {
    unsigned long long r;
    asm("mov.b64 %0, {%1, %2};" : "=l"(r) : "f"(lo), "f"(hi));
    return r;
}
__device__ __forceinline__ void unpack2(unsigned long long v, float& lo, float& hi) {
    asm("mov.b64 {%0, %1}, %2;" : "=f"(lo), "=f"(hi) : "l"(v));
}
__device__ __forceinline__ void fma2(unsigned long long& acc, unsigned long long a,
                                     unsigned long long b) {
    asm("fma.rn.f32x2 %0, %1, %2, %0;" : "+l"(acc) : "l"(a), "l"(b));
}

// ---------------- kA: voxelize + packed cnt/sum_xyz ----------------
__global__ void kA(const float* __restrict__ pts) {
    int b = blockIdx.y;
    int i = blockIdx.x * blockDim.x + threadIdx.x;
    if (i >= NP) return;
    const float* p = pts + ((long)b * NP + i) * 3;
    float p0 = p[0], p1 = p[1], p2 = p[2];
    float fx = floorf((p0 + 51.2f) / 0.2f);
    float fy = floorf((p1 + 51.2f) / 0.2f);
    float fz = floorf((p2 + 3.0f) / 6.0f);
    bool valid = (fx >= 0.f) && (fx < 512.f) && (fy >= 0.f) && (fy < 512.f) &&
                 (fz >= 0.f) && (fz < 1.f);
    int vid = HW;
    if (valid) {
        vid = (int)fy * 512 + (int)fx;
        float* pcv = (float*)&g_s.pc[b * NSEG + vid];
        atomicAdd(pcv + 0, p0);
        atomicAdd(pcv + 1, p1);
        atomicAdd(pcv + 2, p2);
        atomicAdd(pcv + 3, 1.0f);
    } else {
        atomicAdd(&g_s.pc[b * NSEG + HW].w, 1.0f);
    }
    g_vid[b * NP + i] = vid;
}

// ---------------- scan ----------------
__device__ __forceinline__ int blockScanExcl(int v, int t, int* ws) {
    int lane = t & 31, w = t >> 5;
    int inc = v;
#pragma unroll
    for (int o = 1; o < 32; o <<= 1) {
        int n = __shfl_up_sync(0xffffffffu, inc, o);
        if (lane >= o) inc += n;
    }
    if (lane == 31) ws[w] = inc;
    __syncthreads();
    if (w == 0) {
        int s = ws[lane];
#pragma unroll
        for (int o = 1; o < 32; o <<= 1) {
            int n = __shfl_up_sync(0xffffffffu, s, o);
            if (lane >= o) s += n;
        }
        ws[lane] = s;
    }
    __syncthreads();
    return (w ? ws[w - 1] : 0) + inc - v;
}

__global__ void kS1() {
    __shared__ int ws[32];
    int t = threadIdx.x;
    int idx = blockIdx.x * SCAN_B + t;
    int v = (idx < SCAN_N) ? (int)g_s.pc[idx].w : 0;
    int ex = blockScanExcl(v, t, ws);
    if (idx < SCAN_N) g_start[idx] = ex;
    if (t == 0) g_bsum[blockIdx.x] = ws[31];
}

__global__ void kS2() {
    __shared__ int ws[32];
    int t = threadIdx.x;
    int v = (t < SCAN_NB) ? g_bsum[t] : 0;
    int ex = blockScanExcl(v, t, ws);
    if (t < SCAN_NB) g_bsum[t] = ex;
}

// ------- kB: feats @ W1 -> x1[CSR slot]; 8 points/warp, reg-accum stats -----
__global__ void kB(const float* __restrict__ pts, const float* __restrict__ W1) {
    __shared__ float w[9 * 32];
    __shared__ float ssum[32], ssq[32];
    int t = threadIdx.x;
    for (int k = t; k < 9 * 32; k += blockDim.x) w[k] = W1[k];
    if (t < 32) { ssum[t] = 0.f; ssq[t] = 0.f; }
    __syncthreads();
    int b = blockIdx.y;
    int warp = t >> 5, c = t & 31;
    int i0 = blockIdx.x * 64 + warp * 8;
    float lsum = 0.f, lsq = 0.f;
#pragma unroll
    for (int r = 0; r < 8; r++) {
        int i = i0 + r;
        if (i >= NP) break;
        int vid = g_vid[b * NP + i];
        int seg = b * NSEG + vid;
        int slot = 0;
        if (c == 0) slot = atomicAdd(&g_start[seg], 1) + g_bsum[seg >> 10];
        slot = __shfl_sync(0xffffffffu, slot, 0);
        float x = 0.f;
        if (vid < HW) {
            const float* p = pts + ((long)b * NP + i) * 3;
            float p0 = p[0], p1 = p[1], p2 = p[2];
            float4 pc = g_s.pc[seg];
            float inv = 1.0f / fmaxf(pc.w, 1.0f);
            float m0 = pc.x * inv, m1 = pc.y * inv, m2 = pc.z * inv;
            int cx = vid & 511, cy = vid >> 9;
            float cpx = -51.2f + ((float)cx + 0.5f) * 0.2f;
            float cpy = -51.2f + ((float)cy + 0.5f) * 0.2f;
            float f[9] = { p0, p1, p2, p0 - m0, p1 - m1, p2 - m2,
                           p0 - cpx, p1 - cpy, p2 };
#pragma unroll
            for (int k = 0; k < 9; k++) x += f[k] * w[k * 32 + c];
        }
        g_x1h[(size_t)slot * 32 + c] = __float2half(x);
        if (c == 0) g_vids[slot] = seg;
        lsum += x; lsq += x * x;
    }
    atomicAdd(&ssum[c], lsum);
    atomicAdd(&ssq[c], lsq);
    __syncthreads();
    if (t < 32) {
        int bk = blockIdx.x & (NBUCK - 1);
        atomicAdd(&g_s.bnb1[bk][b * 64 + t], (double)ssum[t]);
        atomicAdd(&g_s.bnb1[bk][b * 64 + 32 + t], (double)ssq[t]);
    }
}

// ---------------- BN finalize (reduce buckets) ----------------
__global__ void kBN(int which, const float* __restrict__ gam,
                    const float* __restrict__ bet) {
    int t = threadIdx.x;
    int C = which ? 64 : 32;
    int b = t / C, c = t % C;
    if (b >= BB) return;
    float nv = fmaxf((float)NP - g_s.pc[b * NSEG + HW].w, 1.0f);
    double s = 0.0, sq = 0.0;
    if (which) {
        for (int k = 0; k < NBUCK; k++) {
            s += g_s.bnb2[k][b * 128 + c];
            sq += g_s.bnb2[k][b * 128 + 64 + c];
        }
    } else {
        for (int k = 0; k < NBUCK; k++) {
            s += g_s.bnb1[k][b * 64 + c];
            sq += g_s.bnb1[k][b * 64 + 32 + c];
        }
    }
    float mean = (float)(s / (double)nv);
    float var = (float)(sq / (double)nv) - mean * mean;
    var = fmaxf(var, 0.f);
    float sc = gam[c] * rsqrtf(var + 0.001f);
    float sh = bet[c] - mean * sc;
    if (which) { g_bn2ss[b * 128 + c] = sc; g_bn2ss[b * 128 + 64 + c] = sh; }
    else       { g_bn1ss[b * 64 + c] = sc;  g_bn1ss[b * 64 + 32 + c] = sh; }
}

// ------- kP1: mix-pool1, half2 lanes, 2 voxels per warp -------
__global__ void kP1() {
    int b = blockIdx.y;
    int t = threadIdx.x;
    int w = t >> 5, lane = t & 31;
    int v = blockIdx.x * 16 + w * 2 + (lane >> 4);
    int c2 = lane & 15;
    int base = b * NSEG + v;
    int cnt = (int)g_s.pc[base].w;
    if (cnt == 0) return;
    int end = g_start[base] + g_bsum[base >> 10];
    int beg = end - cnt;
    float sc0 = g_bn1ss[b * 64 + 2 * c2],     sh0 = g_bn1ss[b * 64 + 32 + 2 * c2];
    float sc1 = g_bn1ss[b * 64 + 2 * c2 + 1], sh1 = g_bn1ss[b * 64 + 32 + 2 * c2 + 1];
    float s0 = 0.f, m0 = 0.f, s1 = 0.f, m1 = 0.f;
    const __half2* x1h2 = (const __half2*)g_x1h;
    for (int j = beg; j < end; j++) {
        float2 xv = __half22float2(x1h2[(size_t)j * 16 + c2]);
        float y0 = fmaxf(xv.x * sc0 + sh0, 0.f);
        float y1 = fmaxf(xv.y * sc1 + sh1, 0.f);
        s0 += y0; m0 = fmaxf(m0, y0);
        s1 += y1; m1 = fmaxf(m1, y1);
    }
    float invc = 1.0f / (float)cnt;
    ((__half2*)g_p1mixh)[((size_t)b * HW + v) * 16 + c2] =
        __floats2half2_rn(0.5f * (m0 + s0 * invc), 0.5f * (m1 + s1 * invc));
}

// ------- kE: tiled GEMM [64 slots x 64 out x 64 k], f32x2 FMA, BN2 stats ---
__global__ __launch_bounds__(256) void kE(const float* __restrict__ W2) {
    __shared__ float sA[ETILE * 65];
    __shared__ float sW[64 * 64];
    __shared__ int   sB[ETILE];
    __shared__ float ssb[2 * 64], sqb[2 * 64];
    int t = threadIdx.x;
    for (int idx = t; idx < 1024; idx += 256)
        ((float4*)sW)[idx] = ((const float4*)W2)[idx];
    if (t < 128) { ssb[t] = 0.f; sqb[t] = 0.f; }
    int warp = t >> 5, lane = t & 31;
    int tile = blockIdx.x;
#pragma unroll
    for (int r8 = 0; r8 < 8; r8++) {
        int row = warp * 8 + r8;
        int j = tile * ETILE + row;
        float a0 = 0.f, a1 = 0.f;
        int b = 0;
        if (j < NSLOT) {
            int seg = g_vids[j];
            b = (seg >= NSEG) ? 1 : 0;
            int vid = seg - b * NSEG;
            if (vid < HW) {
                float x = __half2float(g_x1h[(size_t)j * 32 + lane]);
                float sc = g_bn1ss[b * 64 + lane], sh = g_bn1ss[b * 64 + 32 + lane];
                a0 = fmaxf(x * sc + sh, 0.f);
                a1 = __half2float(g_p1mixh[((size_t)b * HW + vid) * 32 + lane]);
            }
        }
        sA[row * 65 + lane] = a0;
        sA[row * 65 + 32 + lane] = a1;
        if (lane == 0) sB[row] = b;
    }
    __syncthreads();

    int ty = t >> 4, tx = t & 15;     // 16x16 thread grid: 4 rows x 4 cols each
    unsigned long long acc01[4], acc23[4];
#pragma unroll
    for (int p = 0; p < 4; p++) { acc01[p] = pack2(0.f, 0.f); acc23[p] = pack2(0.f, 0.f); }
    const float* Ar = &sA[(ty * 4) * 65];
#pragma unroll 8
    for (int k = 0; k < 64; k++) {
        float4 wv = *(const float4*)&sW[k * 64 + tx * 4];
        unsigned long long w01 = pack2(wv.x, wv.y);
        unsigned long long w23 = pack2(wv.z, wv.w);
#pragma unroll
        for (int p = 0; p < 4; p++) {
            float av = Ar[p * 65 + k];
            unsigned long long a2 = pack2(av, av);
            fma2(acc01[p], a2, w01);
            fma2(acc23[p], a2, w23);
        }
    }

    // write x2 (half2 pairs) + per-thread stats split by batch
    float s0[4] = {0,0,0,0}, q0[4] = {0,0,0,0};
    float s1[4] = {0,0,0,0}, q1[4] = {0,0,0,0};
#pragma unroll
    for (int p = 0; p < 4; p++) {
        int row = ty * 4 + p;
        int j = tile * ETILE + row;
        if (j < NSLOT) {
            float a, bq, cq, dq;
            unpack2(acc01[p], a, bq);
            unpack2(acc23[p], cq, dq);
            __half2* dst = (__half2*)&g_x2h[(size_t)j * 64 + tx * 4];
            dst[0] = __floats2half2_rn(a, bq);
            dst[1] = __floats2half2_rn(cq, dq);
            float vv[4] = { a, bq, cq, dq };
            if (sB[row] == 0) {
#pragma unroll
                for (int q = 0; q < 4; q++) { s0[q] += vv[q]; q0[q] += vv[q] * vv[q]; }
            } else {
#pragma unroll
                for (int q = 0; q < 4; q++) { s1[q] += vv[q]; q1[q] += vv[q] * vv[q]; }
            }
        }
    }
#pragma unroll
    for (int q = 0; q < 4; q++) {
        atomicAdd(&ssb[tx * 4 + q], s0[q]);
        atomicAdd(&sqb[tx * 4 + q], q0[q]);
        atomicAdd(&ssb[64 + tx * 4 + q], s1[q]);
        atomicAdd(&sqb[64 + tx * 4 + q], q1[q]);
    }
    __syncthreads();
    if (t < 128) {
        int b = t >> 6, c = t & 63;
        int bk = blockIdx.x & (NBUCK - 1);
        atomicAdd(&g_s.bnb2[bk][b * 128 + c], (double)ssb[t]);
        atomicAdd(&g_s.bnb2[bk][b * 128 + 64 + c], (double)sqb[t]);
    }
}

// ------- kP2T: CSR mix-pool2 (contiguous rows) + transpose out -------
__global__ void kP2T(float* __restrict__ out) {
    __shared__ float sT[64][33];
    int b = blockIdx.y, t = threadIdx.x;
    int vb = blockIdx.x * 32;
    int sub = t >> 6, c = t & 63;
    float sc = g_bn2ss[b * 128 + c], sh = g_bn2ss[b * 128 + 64 + c];
#pragma unroll
    for (int g8 = 0; g8 < 8; g8++) {
        int v = vb + g8 * 4 + sub;
        int base = b * NSEG + v;
        int cnt = (int)g_s.pc[base].w;
        float val = 0.f;
        if (cnt > 0) {
            int end = g_start[base] + g_bsum[base >> 10];
            int beg = end - cnt;
            float s = 0.f, m = 0.f;
            for (int j = beg; j < end; j++) {
                float x = __half2float(g_x2h[(size_t)j * 64 + c]);
                float y = fmaxf(x * sc + sh, 0.f);
                s += y; m = fmaxf(m, y);
            }
            val = 0.5f * (m + s / (float)cnt);
        }
        sT[c][g8 * 4 + sub] = val;
    }
    __syncthreads();
#pragma unroll
    for (int r = 0; r < 8; r++) {
        int j = t + 256 * r;
        int cc = j >> 5, v = j & 31;
        out[((size_t)b * 64 + cc) * HW + vb + v] = sT[cc][v];
    }
}

extern "C" void kernel_launch(void* const* d_in, const int* in_sizes, int n_in,
                              void* d_out, int out_size) {
    const float* pts = (const float*)d_in[0];
    const float* W1 = (const float*)d_in[1];
    const float* g1 = (const float*)d_in[2];
    const float* b1 = (const float*)d_in[3];
    const float* W2 = (const float*)d_in[4];
    const float* g2 = (const float*)d_in[5];
    const float* b2 = (const float*)d_in[6];
    float* out = (float*)d_out;

    void* sp = nullptr;
    cudaGetSymbolAddress(&sp, g_s);
    cudaMemsetAsync(sp, 0, sizeof(Scratch));

    dim3 gA((NP + 255) / 256, BB);
    kA<<<gA, 256>>>(pts);

    kS1<<<SCAN_NB, SCAN_B>>>();
    kS2<<<1, SCAN_B>>>();

    dim3 gB((NP + 63) / 64, BB);
    kB<<<gB, 256>>>(pts, W1);

    kBN<<<1, BB * 32>>>(0, g1, b1);

    dim3 gP1(HW / 16, BB);
    kP1<<<gP1, 256>>>();

    kE<<<ETILES, 256>>>(W2);

    kBN<<<1, BB * 64>>>(1, g2, b2);

    dim3 gP2(HW / 32, BB);
    kP2T<<<gP2, 256>>>(out);
}

// round 14
// speedup vs baseline: 3.7324x; 1.0238x over previous
#include <cuda_runtime.h>
#include <cuda_bf16.h>
#include <cuda_fp16.h>
#include <math.h>

#define BB 2
#define NP 150000
#define NSLOT (BB * NP)
#define HW 262144
#define NSEG (HW + 1)
#define SCAN_N (BB * NSEG)
#define SCAN_B 1024
#define SCAN_NB ((SCAN_N + SCAN_B - 1) / SCAN_B)
#define NBUCK 128
#define ETILE 64
#define ETILES ((NSLOT + ETILE - 1) / ETILE)

struct Scratch {
    double bnb1[NBUCK][BB * 64];    // buckets: [b][ sum(32) | sumsq(32) ]
    double bnb2[NBUCK][BB * 128];   // buckets: [b][ sum(64) | sumsq(64) ]
    float4 pc[BB * NSEG];           // {sum_x, sum_y, sum_z, count}
};

__device__ Scratch g_s;
__device__ int    g_start[SCAN_N];    // local-block exclusive scan; after kB: local end
__device__ int    g_bsum[SCAN_NB];    // exclusive scan of block sums
__device__ int    g_vids[NSLOT];      // per CSR slot: seg = b*NSEG+vid
__device__ __half g_x1h[(size_t)NSLOT * 32];      // CSR-ordered, raw (pre-BN)
__device__ __half g_x2h[(size_t)NSLOT * 64];      // CSR-ordered, raw (pre-BN)
__device__ __half g_p1mixh[(size_t)BB * HW * 32]; // occupied voxels only
__device__ float  g_bn1ss[BB * 64];   // [b][ scale(32) | shift(32) ]
__device__ float  g_bn2ss[BB * 128];  // [b][ scale(64) | shift(64) ]

// ---- packed f32x2 helpers (Blackwell FFMA2) ----
__device__ __forceinline__ unsigned long long pack2(float lo, float hi) {
    unsigned long long r;
    asm("mov.b64 %0, {%1, %2};" : "=l"(r) : "f"(lo), "f"(hi));
    return r;
}
__device__ __forceinline__ void unpack2(unsigned long long v, float& lo, float& hi) {
    asm("mov.b64 {%0, %1}, %2;" : "=f"(lo), "=f"(hi) : "l"(v));
}
__device__ __forceinline__ void fma2(unsigned long long& acc, unsigned long long a,
                                     unsigned long long b) {
    asm("fma.rn.f32x2 %0, %1, %2, %0;" : "+l"(acc) : "l"(a), "l"(b));
}

__device__ __forceinline__ int voxel_of(float p0, float p1, float p2) {
    float fx = floorf((p0 + 51.2f) / 0.2f);
    float fy = floorf((p1 + 51.2f) / 0.2f);
    float fz = floorf((p2 + 3.0f) / 6.0f);
    bool valid = (fx >= 0.f) && (fx < 512.f) && (fy >= 0.f) && (fy < 512.f) &&
                 (fz >= 0.f) && (fz < 1.f);
    return valid ? ((int)fy * 512 + (int)fx) : HW;
}

// ---------------- kA: voxelize + packed cnt/sum_xyz ----------------
__global__ void kA(const float* __restrict__ pts) {
    int b = blockIdx.y;
    int i = blockIdx.x * blockDim.x + threadIdx.x;
    if (i >= NP) return;
    const float* p = pts + ((long)b * NP + i) * 3;
    float p0 = p[0], p1 = p[1], p2 = p[2];
    int vid = voxel_of(p0, p1, p2);
    if (vid < HW) {
        float* pcv = (float*)&g_s.pc[b * NSEG + vid];
        atomicAdd(pcv + 0, p0);
        atomicAdd(pcv + 1, p1);
        atomicAdd(pcv + 2, p2);
        atomicAdd(pcv + 3, 1.0f);
    } else {
        atomicAdd(&g_s.pc[b * NSEG + HW].w, 1.0f);
    }
}

// ---------------- scan ----------------
__device__ __forceinline__ int blockScanExcl(int v, int t, int* ws) {
    int lane = t & 31, w = t >> 5;
    int inc = v;
#pragma unroll
    for (int o = 1; o < 32; o <<= 1) {
        int n = __shfl_up_sync(0xffffffffu, inc, o);
        if (lane >= o) inc += n;
    }
    if (lane == 31) ws[w] = inc;
    __syncthreads();
    if (w == 0) {
        int s = ws[lane];
#pragma unroll
        for (int o = 1; o < 32; o <<= 1) {
            int n = __shfl_up_sync(0xffffffffu, s, o);
            if (lane >= o) s += n;
        }
        ws[lane] = s;
    }
    __syncthreads();
    return (w ? ws[w - 1] : 0) + inc - v;
}

__global__ void kS1() {
    __shared__ int ws[32];
    int t = threadIdx.x;
    int idx = blockIdx.x * SCAN_B + t;
    int v = (idx < SCAN_N) ? (int)g_s.pc[idx].w : 0;
    int ex = blockScanExcl(v, t, ws);
    if (idx < SCAN_N) g_start[idx] = ex;
    if (t == 0) g_bsum[blockIdx.x] = ws[31];
}

__global__ void kS2() {
    __shared__ int ws[32];
    int t = threadIdx.x;
    int v = (t < SCAN_NB) ? g_bsum[t] : 0;
    int ex = blockScanExcl(v, t, ws);
    if (t < SCAN_NB) g_bsum[t] = ex;
}

// ------- kB: feats @ W1 -> x1[CSR slot]; lane-owned points, shfl distribute --
__global__ void kB(const float* __restrict__ pts, const float* __restrict__ W1) {
    __shared__ float w[9 * 32];
    __shared__ float ssum[32], ssq[32];
    int t = threadIdx.x;
    for (int k = t; k < 9 * 32; k += blockDim.x) w[k] = W1[k];
    if (t < 32) { ssum[t] = 0.f; ssq[t] = 0.f; }
    __syncthreads();
    int b = blockIdx.y;
    int warp = t >> 5, c = t & 31;
    int i0 = blockIdx.x * 64 + warp * 8;

    // lanes 0-7 own points i0+lane: load coords, compute vid, claim slot, load pc
    float q0 = 0.f, q1 = 0.f, q2 = 0.f;
    int vidr = HW, slotr = 0;
    float4 pcr = make_float4(0.f, 0.f, 0.f, 1.f);
    if (c < 8) {
        int i = i0 + c;
        if (i < NP) {
            const float* p = pts + ((long)b * NP + i) * 3;
            q0 = p[0]; q1 = p[1]; q2 = p[2];
            vidr = voxel_of(q0, q1, q2);
            int seg = b * NSEG + vidr;
            slotr = atomicAdd(&g_start[seg], 1) + g_bsum[seg >> 10];
            g_vids[slotr] = seg;
            if (vidr < HW) pcr = g_s.pc[seg];
        }
    }

    float lsum = 0.f, lsq = 0.f;
#pragma unroll
    for (int r = 0; r < 8; r++) {
        int i = i0 + r;
        if (i >= NP) break;
        int vv = __shfl_sync(0xffffffffu, vidr, r);
        int sl = __shfl_sync(0xffffffffu, slotr, r);
        float x = 0.f;
        if (vv < HW) {
            float p0 = __shfl_sync(0xffffffffu, q0, r);
            float p1 = __shfl_sync(0xffffffffu, q1, r);
            float p2 = __shfl_sync(0xffffffffu, q2, r);
            float px = __shfl_sync(0xffffffffu, pcr.x, r);
            float py = __shfl_sync(0xffffffffu, pcr.y, r);
            float pz = __shfl_sync(0xffffffffu, pcr.z, r);
            float pw = __shfl_sync(0xffffffffu, pcr.w, r);
            float inv = 1.0f / fmaxf(pw, 1.0f);
            float m0 = px * inv, m1 = py * inv, m2 = pz * inv;
            int cx = vv & 511, cy = vv >> 9;
            float cpx = -51.2f + ((float)cx + 0.5f) * 0.2f;
            float cpy = -51.2f + ((float)cy + 0.5f) * 0.2f;
            float f[9] = { p0, p1, p2, p0 - m0, p1 - m1, p2 - m2,
                           p0 - cpx, p1 - cpy, p2 };
#pragma unroll
            for (int k = 0; k < 9; k++) x += f[k] * w[k * 32 + c];
        }
        g_x1h[(size_t)sl * 32 + c] = __float2half(x);
        lsum += x; lsq += x * x;
    }
    atomicAdd(&ssum[c], lsum);
    atomicAdd(&ssq[c], lsq);
    __syncthreads();
    if (t < 32) {
        int bk = blockIdx.x & (NBUCK - 1);
        atomicAdd(&g_s.bnb1[bk][b * 64 + t], (double)ssum[t]);
        atomicAdd(&g_s.bnb1[bk][b * 64 + 32 + t], (double)ssq[t]);
    }
}

// ---------------- BN finalize (reduce buckets) ----------------
__global__ void kBN(int which, const float* __restrict__ gam,
                    const float* __restrict__ bet) {
    int t = threadIdx.x;
    int C = which ? 64 : 32;
    int b = t / C, c = t % C;
    if (b >= BB) return;
    float nv = fmaxf((float)NP - g_s.pc[b * NSEG + HW].w, 1.0f);
    double s = 0.0, sq = 0.0;
    if (which) {
        for (int k = 0; k < NBUCK; k++) {
            s += g_s.bnb2[k][b * 128 + c];
            sq += g_s.bnb2[k][b * 128 + 64 + c];
        }
    } else {
        for (int k = 0; k < NBUCK; k++) {
            s += g_s.bnb1[k][b * 64 + c];
            sq += g_s.bnb1[k][b * 64 + 32 + c];
        }
    }
    float mean = (float)(s / (double)nv);
    float var = (float)(sq / (double)nv) - mean * mean;
    var = fmaxf(var, 0.f);
    float sc = gam[c] * rsqrtf(var + 0.001f);
    float sh = bet[c] - mean * sc;
    if (which) { g_bn2ss[b * 128 + c] = sc; g_bn2ss[b * 128 + 64 + c] = sh; }
    else       { g_bn1ss[b * 64 + c] = sc;  g_bn1ss[b * 64 + 32 + c] = sh; }
}

// ------- kP1: mix-pool1, half2 lanes, 2 voxels per warp -------
__global__ void kP1() {
    int b = blockIdx.y;
    int t = threadIdx.x;
    int w = t >> 5, lane = t & 31;
    int v = blockIdx.x * 16 + w * 2 + (lane >> 4);
    int c2 = lane & 15;
    int base = b * NSEG + v;
    int cnt = (int)g_s.pc[base].w;
    if (cnt == 0) return;
    int end = g_start[base] + g_bsum[base >> 10];
    int beg = end - cnt;
    float sc0 = g_bn1ss[b * 64 + 2 * c2],     sh0 = g_bn1ss[b * 64 + 32 + 2 * c2];
    float sc1 = g_bn1ss[b * 64 + 2 * c2 + 1], sh1 = g_bn1ss[b * 64 + 32 + 2 * c2 + 1];
    float s0 = 0.f, m0 = 0.f, s1 = 0.f, m1 = 0.f;
    const __half2* x1h2 = (const __half2*)g_x1h;
    for (int j = beg; j < end; j++) {
        float2 xv = __half22float2(x1h2[(size_t)j * 16 + c2]);
        float y0 = fmaxf(xv.x * sc0 + sh0, 0.f);
        float y1 = fmaxf(xv.y * sc1 + sh1, 0.f);
        s0 += y0; m0 = fmaxf(m0, y0);
        s1 += y1; m1 = fmaxf(m1, y1);
    }
    float invc = 1.0f / (float)cnt;
    ((__half2*)g_p1mixh)[((size_t)b * HW + v) * 16 + c2] =
        __floats2half2_rn(0.5f * (m0 + s0 * invc), 0.5f * (m1 + s1 * invc));
}

// ------- kE: tiled GEMM [64 slots x 64 out x 64 k], f32x2 FMA, BN2 stats ---
__global__ __launch_bounds__(256) void kE(const float* __restrict__ W2) {
    __shared__ float sA[ETILE * 65];
    __shared__ float sW[64 * 64];
    __shared__ int   sB[ETILE];
    __shared__ float ssb[2 * 64], sqb[2 * 64];
    int t = threadIdx.x;
    for (int idx = t; idx < 1024; idx += 256)
        ((float4*)sW)[idx] = ((const float4*)W2)[idx];
    if (t < 128) { ssb[t] = 0.f; sqb[t] = 0.f; }
    int warp = t >> 5, lane = t & 31;
    int tile = blockIdx.x;
#pragma unroll
    for (int r8 = 0; r8 < 8; r8++) {
        int row = warp * 8 + r8;
        int j = tile * ETILE + row;
        float a0 = 0.f, a1 = 0.f;
        int b = 0;
        if (j < NSLOT) {
            int seg = g_vids[j];
            b = (seg >= NSEG) ? 1 : 0;
            int vid = seg - b * NSEG;
            if (vid < HW) {
                float x = __half2float(g_x1h[(size_t)j * 32 + lane]);
                float sc = g_bn1ss[b * 64 + lane], sh = g_bn1ss[b * 64 + 32 + lane];
                a0 = fmaxf(x * sc + sh, 0.f);
                a1 = __half2float(g_p1mixh[((size_t)b * HW + vid) * 32 + lane]);
            }
        }
        sA[row * 65 + lane] = a0;
        sA[row * 65 + 32 + lane] = a1;
        if (lane == 0) sB[row] = b;
    }
    __syncthreads();

    int ty = t >> 4, tx = t & 15;     // 16x16 thread grid: 4 rows x 4 cols each
    unsigned long long acc01[4], acc23[4];
#pragma unroll
    for (int p = 0; p < 4; p++) { acc01[p] = pack2(0.f, 0.f); acc23[p] = pack2(0.f, 0.f); }
    const float* Ar = &sA[(ty * 4) * 65];
#pragma unroll 8
    for (int k = 0; k < 64; k++) {
        float4 wv = *(const float4*)&sW[k * 64 + tx * 4];
        unsigned long long w01 = pack2(wv.x, wv.y);
        unsigned long long w23 = pack2(wv.z, wv.w);
#pragma unroll
        for (int p = 0; p < 4; p++) {
            float av = Ar[p * 65 + k];
            unsigned long long a2 = pack2(av, av);
            fma2(acc01[p], a2, w01);
            fma2(acc23[p], a2, w23);
        }
    }

    // write x2 (half2 pairs) + per-thread stats split by batch
    float s0[4] = {0,0,0,0}, q0[4] = {0,0,0,0};
    float s1[4] = {0,0,0,0}, q1[4] = {0,0,0,0};
#pragma unroll
    for (int p = 0; p < 4; p++) {
        int row = ty * 4 + p;
        int j = tile * ETILE + row;
        if (j < NSLOT) {
            float a, bq, cq, dq;
            unpack2(acc01[p], a, bq);
            unpack2(acc23[p], cq, dq);
            __half2* dst = (__half2*)&g_x2h[(size_t)j * 64 + tx * 4];
            dst[0] = __floats2half2_rn(a, bq);
            dst[1] = __floats2half2_rn(cq, dq);
            float vv[4] = { a, bq, cq, dq };
            if (sB[row] == 0) {
#pragma unroll
                for (int q = 0; q < 4; q++) { s0[q] += vv[q]; q0[q] += vv[q] * vv[q]; }
            } else {
#pragma unroll
                for (int q = 0; q < 4; q++) { s1[q] += vv[q]; q1[q] += vv[q] * vv[q]; }
            }
        }
    }
#pragma unroll
    for (int q = 0; q < 4; q++) {
        atomicAdd(&ssb[tx * 4 + q], s0[q]);
        atomicAdd(&sqb[tx * 4 + q], q0[q]);
        atomicAdd(&ssb[64 + tx * 4 + q], s1[q]);
        atomicAdd(&sqb[64 + tx * 4 + q], q1[q]);
    }
    __syncthreads();
    if (t < 128) {
        int b = t >> 6, c = t & 63;
        int bk = blockIdx.x & (NBUCK - 1);
        atomicAdd(&g_s.bnb2[bk][b * 128 + c], (double)ssb[t]);
        atomicAdd(&g_s.bnb2[bk][b * 128 + 64 + c], (double)sqb[t]);
    }
}

// ------- kP2T: CSR mix-pool2 (contiguous rows) + transpose out -------
__global__ void kP2T(float* __restrict__ out) {
    __shared__ float sT[64][33];
    int b = blockIdx.y, t = threadIdx.x;
    int vb = blockIdx.x * 32;
    int sub = t >> 6, c = t & 63;
    float sc = g_bn2ss[b * 128 + c], sh = g_bn2ss[b * 128 + 64 + c];
#pragma unroll
    for (int g8 = 0; g8 < 8; g8++) {
        int v = vb + g8 * 4 + sub;
        int base = b * NSEG + v;
        int cnt = (int)g_s.pc[base].w;
        float val = 0.f;
        if (cnt > 0) {
            int end = g_start[base] + g_bsum[base >> 10];
            int beg = end - cnt;
            float s = 0.f, m = 0.f;
            for (int j = beg; j < end; j++) {
                float x = __half2float(g_x2h[(size_t)j * 64 + c]);
                float y = fmaxf(x * sc + sh, 0.f);
                s += y; m = fmaxf(m, y);
            }
            val = 0.5f * (m + s / (float)cnt);
        }
        sT[c][g8 * 4 + sub] = val;
    }
    __syncthreads();
#pragma unroll
    for (int r = 0; r < 8; r++) {
        int j = t + 256 * r;
        int cc = j >> 5, v = j & 31;
        out[((size_t)b * 64 + cc) * HW + vb + v] = sT[cc][v];
    }
}

extern "C" void kernel_launch(void* const* d_in, const int* in_sizes, int n_in,
                              void* d_out, int out_size) {
    const float* pts = (const float*)d_in[0];
    const float* W1 = (const float*)d_in[1];
    const float* g1 = (const float*)d_in[2];
    const float* b1 = (const float*)d_in[3];
    const float* W2 = (const float*)d_in[4];
    const float* g2 = (const float*)d_in[5];
    const float* b2 = (const float*)d_in[6];
    float* out = (float*)d_out;

    void* sp = nullptr;
    cudaGetSymbolAddress(&sp, g_s);
    cudaMemsetAsync(sp, 0, sizeof(Scratch));

    dim3 gA((NP + 255) / 256, BB);
    kA<<<gA, 256>>>(pts);

    kS1<<<SCAN_NB, SCAN_B>>>();
    kS2<<<1, SCAN_B>>>();

    dim3 gB((NP + 63) / 64, BB);
    kB<<<gB, 256>>>(pts, W1);

    kBN<<<1, BB * 32>>>(0, g1, b1);

    dim3 gP1(HW / 16, BB);
    kP1<<<gP1, 256>>>();

    kE<<<ETILES, 256>>>(W2);

    kBN<<<1, BB * 64>>>(1, g2, b2);

    dim3 gP2(HW / 32, BB);
    kP2T<<<gP2, 256>>>(out);
}

// round 17
// speedup vs baseline: 3.9190x; 1.0500x over previous
#include <cuda_runtime.h>
#include <cuda_bf16.h>
#include <cuda_fp16.h>
#include <math.h>

#define BB 2
#define NP 150000
#define NSLOT (BB * NP)
#define HW 262144
#define NSEG (HW + 1)
#define SCAN_N (BB * NSEG)
#define SCAN_B 1024
#define SCAN_NB ((SCAN_N + SCAN_B - 1) / SCAN_B)
#define NBUCK 128
#define ETILE 64
#define ETILES ((NSLOT + ETILE - 1) / ETILE)
#define SAP 68   // sA row stride (floats): 16B-aligned rows, conflict-safe

struct Scratch {
    double bnb1[NBUCK][BB * 64];    // buckets: [b][ sum(32) | sumsq(32) ]
    double bnb2[NBUCK][BB * 128];   // buckets: [b][ sum(64) | sumsq(64) ]
    float4 pc[BB * NSEG];           // {sum_x, sum_y, sum_z, count}
};

__device__ Scratch g_s;
__device__ int    g_start[SCAN_N];    // local-block exclusive scan; after kB: local end
__device__ int    g_bsum[SCAN_NB];    // exclusive scan of block sums
__device__ int    g_vids[NSLOT];      // per CSR slot: seg = b*NSEG+vid
__device__ __half g_x1h[(size_t)NSLOT * 32];      // CSR-ordered, raw (pre-BN)
__device__ __half g_x2h[(size_t)NSLOT * 64];      // CSR-ordered, raw (pre-BN)
__device__ __half g_p1mixh[(size_t)BB * HW * 32]; // occupied voxels only
__device__ float  g_bn1ss[BB * 64];   // [b][ scale(32) | shift(32) ]
__device__ float  g_bn2ss[BB * 128];  // [b][ scale(64) | shift(64) ]

// ---- packed f32x2 helpers (Blackwell FFMA2) ----
__device__ __forceinline__ unsigned long long pack2(float lo, float hi) {
    unsigned long long r;
    asm("mov.b64 %0, {%1, %2};" : "=l"(r) : "f"(lo), "f"(hi));
    return r;
}
__device__ __forceinline__ void unpack2(unsigned long long v, float& lo, float& hi) {
    asm("mov.b64 {%0, %1}, %2;" : "=f"(lo), "=f"(hi) : "l"(v));
}
__device__ __forceinline__ void fma2(unsigned long long& acc, unsigned long long a,
                                     unsigned long long b) {
    asm("fma.rn.f32x2 %0, %1, %2, %0;" : "+l"(acc) : "l"(a), "l"(b));
}

__device__ __forceinline__ int voxel_of(float p0, float p1, float p2) {
    float fx = floorf((p0 + 51.2f) / 0.2f);
    float fy = floorf((p1 + 51.2f) / 0.2f);
    float fz = floorf((p2 + 3.0f) / 6.0f);
    bool valid = (fx >= 0.f) && (fx < 512.f) && (fy >= 0.f) && (fy < 512.f) &&
                 (fz >= 0.f) && (fz < 1.f);
    return valid ? ((int)fy * 512 + (int)fx) : HW;
}

// ---------------- kA: voxelize + packed cnt/sum_xyz ----------------
__global__ void kA(const float* __restrict__ pts) {
    int b = blockIdx.y;
    int i = blockIdx.x * blockDim.x + threadIdx.x;
    if (i >= NP) return;
    const float* p = pts + ((long)b * NP + i) * 3;
    float p0 = p[0], p1 = p[1], p2 = p[2];
    int vid = voxel_of(p0, p1, p2);
    if (vid < HW) {
        float* pcv = (float*)&g_s.pc[b * NSEG + vid];
        atomicAdd(pcv + 0, p0);
        atomicAdd(pcv + 1, p1);
        atomicAdd(pcv + 2, p2);
        atomicAdd(pcv + 3, 1.0f);
    } else {
        atomicAdd(&g_s.pc[b * NSEG + HW].w, 1.0f);
    }
}

// ---------------- scan ----------------
__device__ __forceinline__ int blockScanExcl(int v, int t, int* ws) {
    int lane = t & 31, w = t >> 5;
    int inc = v;
#pragma unroll
    for (int o = 1; o < 32; o <<= 1) {
        int n = __shfl_up_sync(0xffffffffu, inc, o);
        if (lane >= o) inc += n;
    }
    if (lane == 31) ws[w] = inc;
    __syncthreads();
    if (w == 0) {
        int s = ws[lane];
#pragma unroll
        for (int o = 1; o < 32; o <<= 1) {
            int n = __shfl_up_sync(0xffffffffu, s, o);
            if (lane >= o) s += n;
        }
        ws[lane] = s;
    }
    __syncthreads();
    return (w ? ws[w - 1] : 0) + inc - v;
}

__global__ void kS1() {
    __shared__ int ws[32];
    int t = threadIdx.x;
    int idx = blockIdx.x * SCAN_B + t;
    int v = (idx < SCAN_N) ? (int)g_s.pc[idx].w : 0;
    int ex = blockScanExcl(v, t, ws);
    if (idx < SCAN_N) g_start[idx] = ex;
    if (t == 0) g_bsum[blockIdx.x] = ws[31];
}

__global__ void kS2() {
    __shared__ int ws[32];
    int t = threadIdx.x;
    int v = (t < SCAN_NB) ? g_bsum[t] : 0;
    int ex = blockScanExcl(v, t, ws);
    if (t < SCAN_NB) g_bsum[t] = ex;
}

// ------- kB: feats @ W1 -> x1[CSR slot]; lane-owned points, shfl distribute --
__global__ void kB(const float* __restrict__ pts, const float* __restrict__ W1) {
    __shared__ float w[9 * 32];
    __shared__ float ssum[32], ssq[32];
    int t = threadIdx.x;
    for (int k = t; k < 9 * 32; k += blockDim.x) w[k] = W1[k];
    if (t < 32) { ssum[t] = 0.f; ssq[t] = 0.f; }
    __syncthreads();
    int b = blockIdx.y;
    int warp = t >> 5, c = t & 31;
    int i0 = blockIdx.x * 64 + warp * 8;

    float q0 = 0.f, q1 = 0.f, q2 = 0.f;
    int vidr = HW, slotr = 0;
    float4 pcr = make_float4(0.f, 0.f, 0.f, 1.f);
    if (c < 8) {
        int i = i0 + c;
        if (i < NP) {
            const float* p = pts + ((long)b * NP + i) * 3;
            q0 = p[0]; q1 = p[1]; q2 = p[2];
            vidr = voxel_of(q0, q1, q2);
            int seg = b * NSEG + vidr;
            slotr = atomicAdd(&g_start[seg], 1) + g_bsum[seg >> 10];
            g_vids[slotr] = seg;
            if (vidr < HW) pcr = g_s.pc[seg];
        }
    }

    float lsum = 0.f, lsq = 0.f;
#pragma unroll
    for (int r = 0; r < 8; r++) {
        int i = i0 + r;
        if (i >= NP) break;
        int vv = __shfl_sync(0xffffffffu, vidr, r);
        int sl = __shfl_sync(0xffffffffu, slotr, r);
        float x = 0.f;
        if (vv < HW) {
            float p0 = __shfl_sync(0xffffffffu, q0, r);
            float p1 = __shfl_sync(0xffffffffu, q1, r);
            float p2 = __shfl_sync(0xffffffffu, q2, r);
            float px = __shfl_sync(0xffffffffu, pcr.x, r);
            float py = __shfl_sync(0xffffffffu, pcr.y, r);
            float pz = __shfl_sync(0xffffffffu, pcr.z, r);
            float pw = __shfl_sync(0xffffffffu, pcr.w, r);
            float inv = 1.0f / fmaxf(pw, 1.0f);
            float m0 = px * inv, m1 = py * inv, m2 = pz * inv;
            int cx = vv & 511, cy = vv >> 9;
            float cpx = -51.2f + ((float)cx + 0.5f) * 0.2f;
            float cpy = -51.2f + ((float)cy + 0.5f) * 0.2f;
            float f[9] = { p0, p1, p2, p0 - m0, p1 - m1, p2 - m2,
                           p0 - cpx, p1 - cpy, p2 };
#pragma unroll
            for (int k = 0; k < 9; k++) x += f[k] * w[k * 32 + c];
        }
        g_x1h[(size_t)sl * 32 + c] = __float2half(x);
        lsum += x; lsq += x * x;
    }
    atomicAdd(&ssum[c], lsum);
    atomicAdd(&ssq[c], lsq);
    __syncthreads();
    if (t < 32) {
        int bk = blockIdx.x & (NBUCK - 1);
        atomicAdd(&g_s.bnb1[bk][b * 64 + t], (double)ssum[t]);
        atomicAdd(&g_s.bnb1[bk][b * 64 + 32 + t], (double)ssq[t]);
    }
}

// ---------------- BN finalize (reduce buckets) ----------------
__global__ void kBN(int which, const float* __restrict__ gam,
                    const float* __restrict__ bet) {
    int t = threadIdx.x;
    int C = which ? 64 : 32;
    int b = t / C, c = t % C;
    if (b >= BB) return;
    float nv = fmaxf((float)NP - g_s.pc[b * NSEG + HW].w, 1.0f);
    double s = 0.0, sq = 0.0;
    if (which) {
        for (int k = 0; k < NBUCK; k++) {
            s += g_s.bnb2[k][b * 128 + c];
            sq += g_s.bnb2[k][b * 128 + 64 + c];
        }
    } else {
        for (int k = 0; k < NBUCK; k++) {
            s += g_s.bnb1[k][b * 64 + c];
            sq += g_s.bnb1[k][b * 64 + 32 + c];
        }
    }
    float mean = (float)(s / (double)nv);
    float var = (float)(sq / (double)nv) - mean * mean;
    var = fmaxf(var, 0.f);
    float sc = gam[c] * rsqrtf(var + 0.001f);
    float sh = bet[c] - mean * sc;
    if (which) { g_bn2ss[b * 128 + c] = sc; g_bn2ss[b * 128 + 64 + c] = sh; }
    else       { g_bn1ss[b * 64 + c] = sc;  g_bn1ss[b * 64 + 32 + c] = sh; }
}

// ------- kP1: mix-pool1, half2 lanes, 2 voxels per warp -------
__global__ void kP1() {
    int b = blockIdx.y;
    int t = threadIdx.x;
    int w = t >> 5, lane = t & 31;
    int v = blockIdx.x * 16 + w * 2 + (lane >> 4);
    int c2 = lane & 15;
    int base = b * NSEG + v;
    int cnt = (int)g_s.pc[base].w;
    if (cnt == 0) return;
    int end = g_start[base] + g_bsum[base >> 10];
    int beg = end - cnt;
    float sc0 = g_bn1ss[b * 64 + 2 * c2],     sh0 = g_bn1ss[b * 64 + 32 + 2 * c2];
    float sc1 = g_bn1ss[b * 64 + 2 * c2 + 1], sh1 = g_bn1ss[b * 64 + 32 + 2 * c2 + 1];
    float s0 = 0.f, m0 = 0.f, s1 = 0.f, m1 = 0.f;
    const __half2* x1h2 = (const __half2*)g_x1h;
    for (int j = beg; j < end; j++) {
        float2 xv = __half22float2(x1h2[(size_t)j * 16 + c2]);
        float y0 = fmaxf(xv.x * sc0 + sh0, 0.f);
        float y1 = fmaxf(xv.y * sc1 + sh1, 0.f);
        s0 += y0; m0 = fmaxf(m0, y0);
        s1 += y1; m1 = fmaxf(m1, y1);
    }
    float invc = 1.0f / (float)cnt;
    ((__half2*)g_p1mixh)[((size_t)b * HW + v) * 16 + c2] =
        __floats2half2_rn(0.5f * (m0 + s0 * invc), 0.5f * (m1 + s1 * invc));
}

// ------- kE: tiled GEMM [64 slots x 64 out x 64 k], vec-A, f32x2 FMA -------
__global__ __launch_bounds__(256) void kE(const float* __restrict__ W2) {
    __shared__ float sA[ETILE * SAP];
    __shared__ float sW[64 * 64];
    __shared__ int   sB[ETILE];
    __shared__ float ssb[2 * 64], sqb[2 * 64];
    int t = threadIdx.x;
    for (int idx = t; idx < 1024; idx += 256)
        ((float4*)sW)[idx] = ((const float4*)W2)[idx];
    if (t < 128) { ssb[t] = 0.f; sqb[t] = 0.f; }
    int warp = t >> 5, lane = t & 31;
    int tile = blockIdx.x;
#pragma unroll
    for (int r8 = 0; r8 < 8; r8++) {
        int row = warp * 8 + r8;
        int j = tile * ETILE + row;
        float a0 = 0.f, a1 = 0.f;
        int b = 0;
        if (j < NSLOT) {
            int seg = g_vids[j];
            b = (seg >= NSEG) ? 1 : 0;
            int vid = seg - b * NSEG;
            if (vid < HW) {
                float x = __half2float(g_x1h[(size_t)j * 32 + lane]);
                float sc = g_bn1ss[b * 64 + lane], sh = g_bn1ss[b * 64 + 32 + lane];
                a0 = fmaxf(x * sc + sh, 0.f);
                a1 = __half2float(g_p1mixh[((size_t)b * HW + vid) * 32 + lane]);
            }
        }
        sA[row * SAP + lane] = a0;
        sA[row * SAP + 32 + lane] = a1;
        if (lane == 0) sB[row] = b;
    }
    __syncthreads();

    int ty = t >> 4, tx = t & 15;     // 16x16 thread grid: 4 rows x 4 cols each
    unsigned long long acc01[4], acc23[4];
#pragma unroll
    for (int p = 0; p < 4; p++) { acc01[p] = pack2(0.f, 0.f); acc23[p] = pack2(0.f, 0.f); }
    const float* Ar = &sA[(ty * 4) * SAP];
#pragma unroll
    for (int k4 = 0; k4 < 64; k4 += 4) {
        float4 a4[4];
#pragma unroll
        for (int p = 0; p < 4; p++)
            a4[p] = *(const float4*)&Ar[p * SAP + k4];
#pragma unroll
        for (int kk = 0; kk < 4; kk++) {
            int k = k4 + kk;
            float4 wv = *(const float4*)&sW[k * 64 + tx * 4];
            unsigned long long w01 = pack2(wv.x, wv.y);
            unsigned long long w23 = pack2(wv.z, wv.w);
#pragma unroll
            for (int p = 0; p < 4; p++) {
                float av = (kk == 0) ? a4[p].x : (kk == 1) ? a4[p].y :
                           (kk == 2) ? a4[p].z : a4[p].w;
                unsigned long long a2 = pack2(av, av);
                fma2(acc01[p], a2, w01);
                fma2(acc23[p], a2, w23);
            }
        }
    }

    // write x2 (half2 pairs) + per-thread stats split by batch
    float s0[4] = {0,0,0,0}, q0[4] = {0,0,0,0};
    float s1[4] = {0,0,0,0}, q1[4] = {0,0,0,0};
#pragma unroll
    for (int p = 0; p < 4; p++) {
        int row = ty * 4 + p;
        int j = tile * ETILE + row;
        if (j < NSLOT) {
            float a, bq, cq, dq;
            unpack2(acc01[p], a, bq);
            unpack2(acc23[p], cq, dq);
            __half2* dst = (__half2*)&g_x2h[(size_t)j * 64 + tx * 4];
            dst[0] = __floats2half2_rn(a, bq);
            dst[1] = __floats2half2_rn(cq, dq);
            float vv[4] = { a, bq, cq, dq };
            if (sB[row] == 0) {
#pragma unroll
                for (int q = 0; q < 4; q++) { s0[q] += vv[q]; q0[q] += vv[q] * vv[q]; }
            } else {
#pragma unroll
                for (int q = 0; q < 4; q++) { s1[q] += vv[q]; q1[q] += vv[q] * vv[q]; }
            }
        }
    }
#pragma unroll
    for (int q = 0; q < 4; q++) {
        atomicAdd(&ssb[tx * 4 + q], s0[q]);
        atomicAdd(&sqb[tx * 4 + q], q0[q]);
        atomicAdd(&ssb[64 + tx * 4 + q], s1[q]);
        atomicAdd(&sqb[64 + tx * 4 + q], q1[q]);
    }
    __syncthreads();
    if (t < 128) {
        int b = t >> 6, c = t & 63;
        int bk = blockIdx.x & (NBUCK - 1);
        atomicAdd(&g_s.bnb2[bk][b * 128 + c], (double)ssb[t]);
        atomicAdd(&g_s.bnb2[bk][b * 128 + 64 + c], (double)sqb[t]);
    }
}

// ------- kP2T: mix-pool2, half2 lanes (warp per 4 voxels) + transpose out ---
__global__ void kP2T(float* __restrict__ out) {
    __shared__ float sT[64][33];
    int b = blockIdx.y, t = threadIdx.x;
    int vb = blockIdx.x * 32;
    int sub = t >> 5, c2 = t & 31;       // warp sub handles 4 voxels; lane = half2 chan
    float sc0 = g_bn2ss[b * 128 + 2 * c2],     sh0 = g_bn2ss[b * 128 + 64 + 2 * c2];
    float sc1 = g_bn2ss[b * 128 + 2 * c2 + 1], sh1 = g_bn2ss[b * 128 + 64 + 2 * c2 + 1];
    const __half2* x2h2 = (const __half2*)g_x2h;
#pragma unroll
    for (int gi = 0; gi < 4; gi++) {
        int v = vb + sub * 4 + gi;
        int base = b * NSEG + v;
        int cnt = (int)g_s.pc[base].w;
        float v0 = 0.f, v1 = 0.f;
        if (cnt > 0) {
            int end = g_start[base] + g_bsum[base >> 10];
            int beg = end - cnt;
            float s0 = 0.f, m0 = 0.f, s1 = 0.f, m1 = 0.f;
            for (int j = beg; j < end; j++) {
                float2 xv = __half22float2(x2h2[(size_t)j * 32 + c2]);
                float y0 = fmaxf(xv.x * sc0 + sh0, 0.f);
                float y1 = fmaxf(xv.y * sc1 + sh1, 0.f);
                s0 += y0; m0 = fmaxf(m0, y0);
                s1 += y1; m1 = fmaxf(m1, y1);
            }
            float invc = 1.0f / (float)cnt;
            v0 = 0.5f * (m0 + s0 * invc);
            v1 = 0.5f * (m1 + s1 * invc);
        }
        sT[2 * c2][v - vb] = v0;
        sT[2 * c2 + 1][v - vb] = v1;
    }
    __syncthreads();
#pragma unroll
    for (int r = 0; r < 8; r++) {
        int j = t + 256 * r;
        int cc = j >> 5, v = j & 31;
        out[((size_t)b * 64 + cc) * HW + vb + v] = sT[cc][v];
    }
}

extern "C" void kernel_launch(void* const* d_in, const int* in_sizes, int n_in,
                              void* d_out, int out_size) {
    const float* pts = (const float*)d_in[0];
    const float* W1 = (const float*)d_in[1];
    const float* g1 = (const float*)d_in[2];
    const float* b1 = (const float*)d_in[3];
    const float* W2 = (const float*)d_in[4];
    const float* g2 = (const float*)d_in[5];
    const float* b2 = (const float*)d_in[6];
    float* out = (float*)d_out;

    void* sp = nullptr;
    cudaGetSymbolAddress(&sp, g_s);
    cudaMemsetAsync(sp, 0, sizeof(Scratch));

    dim3 gA((NP + 255) / 256, BB);
    kA<<<gA, 256>>>(pts);

    kS1<<<SCAN_NB, SCAN_B>>>();
    kS2<<<1, SCAN_B>>>();

    dim3 gB((NP + 63) / 64, BB);
    kB<<<gB, 256>>>(pts, W1);

    kBN<<<1, BB * 32>>>(0, g1, b1);

    dim3 gP1(HW / 16, BB);
    kP1<<<gP1, 256>>>();

    kE<<<ETILES, 256>>>(W2);

    kBN<<<1, BB * 64>>>(1, g2, b2);

    dim3 gP2(HW / 32, BB);
    kP2T<<<gP2, 256>>>(out);
}